// round 2
// baseline (speedup 1.0000x reference)
#include <cuda_runtime.h>
#include <math.h>

#define WAY  32
#define QRY  128
#define FEAT 640
#define NQ   (WAY*QRY)   // 4096

// Scratch (device globals; no allocation allowed)
__device__ float g_U[WAY*FEAT];
__device__ float g_V[WAY*FEAT];
__device__ float g_CTX[WAY*FEAT];
__device__ float g_Wt[FEAT*WAY];    // w[f][i] = context1^4, f-major
__device__ float g_WS2t[FEAT*WAY];  // 2*w*s,  f-major
__device__ float g_A[WAY];          // sum_f w*s^2

__device__ __forceinline__ float leaky(float x) { return x > 0.f ? x : 0.2f * x; }

// ---------------------------------------------------------------------------
// Kernel 1: U = S @ W1[:, :640]^T, V = S @ W1[:, 640:]^T   (both [32,640])
// grid 160, block 256. Each block: 8 output columns (of combined 1280) x 32 classes.
// S staged in smem transposed St[k][i] (stride 33, conflict-free both directions).
// ---------------------------------------------------------------------------
__global__ void uv_kernel(const float* __restrict__ S, const float* __restrict__ W1) {
    __shared__ float St[320 * 33];
    int tid = threadIdx.x;
    int c = blockIdx.x * 8 + (tid >> 5);   // combined output column 0..1279
    int i = tid & 31;                      // class
    int half = (c >= FEAT) ? 1 : 0;
    int o = c - half * FEAT;
    const float* w1row = W1 + o * (2 * FEAT) + half * FEAT;

    float a0 = 0.f, a1 = 0.f, a2 = 0.f, a3 = 0.f;
    for (int k0 = 0; k0 < FEAT; k0 += 320) {
        __syncthreads();
        for (int idx = tid; idx < WAY * 320; idx += 256) {
            int ii = idx / 320;
            int kk = idx - ii * 320;
            St[kk * 33 + ii] = S[ii * FEAT + k0 + kk];
        }
        __syncthreads();
        #pragma unroll 8
        for (int kk = 0; kk < 320; kk += 4) {
            a0 = fmaf(St[(kk + 0) * 33 + i], __ldg(&w1row[k0 + kk + 0]), a0);
            a1 = fmaf(St[(kk + 1) * 33 + i], __ldg(&w1row[k0 + kk + 1]), a1);
            a2 = fmaf(St[(kk + 2) * 33 + i], __ldg(&w1row[k0 + kk + 2]), a2);
            a3 = fmaf(St[(kk + 3) * 33 + i], __ldg(&w1row[k0 + kk + 3]), a3);
        }
    }
    float acc = (a0 + a1) + (a2 + a3);
    if (half) g_V[i * FEAT + o] = acc;
    else      g_U[i * FEAT + o] = acc;
}

// ---------------------------------------------------------------------------
// Kernel 2: per class i:  x1[p,k] = leaky(U[i,k] + V[j(p),k] + b1[k])  (p<31)
//           x2[p,n] = leaky(sum_k x1[p,k]*W2[n,k] + b2[n])
//           CTX[i,n] = sum_{p<31} x2[p,n]
// grid (10 ntiles, 32 classes), block 128. Tile: M=32 pairs x N=64, K-tiles of 64.
// Thread tile 4p x 4n.
// ---------------------------------------------------------------------------
__global__ void gemm2_kernel(const float* __restrict__ W2, const float* __restrict__ b1,
                             const float* __restrict__ b2) {
    __shared__ float X1s[64 * 36];   // [kk][p], stride 36 (16B-aligned rows, no read conflicts)
    __shared__ float W2s[64 * 68];   // [kk][n], stride 68
    __shared__ float red[8][64];

    int i  = blockIdx.y;
    int n0 = blockIdx.x * 64;
    int tid = threadIdx.x;
    int pq = tid >> 4;    // 0..7
    int nq = tid & 15;    // 0..15

    float acc[4][4];
    #pragma unroll
    for (int a = 0; a < 4; a++)
        #pragma unroll
        for (int b = 0; b < 4; b++) acc[a][b] = 0.f;

    for (int k0 = 0; k0 < FEAT; k0 += 64) {
        // Build X1 tile on the fly (coalesced along k).
        #pragma unroll
        for (int r = 0; r < 16; r++) {
            int idx = r * 128 + tid;       // 0..2047 = 32p x 64k
            int p  = idx >> 6;
            int kk = idx & 63;
            float v = 0.f;
            if (p < 31) {
                int j = (p < i) ? p : p + 1;
                v = leaky(g_U[i * FEAT + k0 + kk] + g_V[j * FEAT + k0 + kk] + b1[k0 + kk]);
            }
            X1s[kk * 36 + p] = v;
        }
        // Load W2 tile transposed (coalesced along k).
        #pragma unroll
        for (int r = 0; r < 32; r++) {
            int idx = r * 128 + tid;       // 0..4095 = 64n x 64k
            int n  = idx >> 6;
            int kk = idx & 63;
            W2s[kk * 68 + n] = W2[(n0 + n) * FEAT + k0 + kk];
        }
        __syncthreads();
        #pragma unroll 8
        for (int kk = 0; kk < 64; kk++) {
            float4 xv = *(const float4*)&X1s[kk * 36 + pq * 4];
            float4 wv = *(const float4*)&W2s[kk * 68 + nq * 4];
            acc[0][0] = fmaf(xv.x, wv.x, acc[0][0]);
            acc[0][1] = fmaf(xv.x, wv.y, acc[0][1]);
            acc[0][2] = fmaf(xv.x, wv.z, acc[0][2]);
            acc[0][3] = fmaf(xv.x, wv.w, acc[0][3]);
            acc[1][0] = fmaf(xv.y, wv.x, acc[1][0]);
            acc[1][1] = fmaf(xv.y, wv.y, acc[1][1]);
            acc[1][2] = fmaf(xv.y, wv.z, acc[1][2]);
            acc[1][3] = fmaf(xv.y, wv.w, acc[1][3]);
            acc[2][0] = fmaf(xv.z, wv.x, acc[2][0]);
            acc[2][1] = fmaf(xv.z, wv.y, acc[2][1]);
            acc[2][2] = fmaf(xv.z, wv.z, acc[2][2]);
            acc[2][3] = fmaf(xv.z, wv.w, acc[2][3]);
            acc[3][0] = fmaf(xv.w, wv.x, acc[3][0]);
            acc[3][1] = fmaf(xv.w, wv.y, acc[3][1]);
            acc[3][2] = fmaf(xv.w, wv.z, acc[3][2]);
            acc[3][3] = fmaf(xv.w, wv.w, acc[3][3]);
        }
        __syncthreads();
    }

    // Epilogue: x2 = leaky(acc + b2), column-sum over valid pairs p<31.
    float psum[4] = {0.f, 0.f, 0.f, 0.f};
    #pragma unroll
    for (int pp = 0; pp < 4; pp++) {
        int p = pq * 4 + pp;
        #pragma unroll
        for (int nn = 0; nn < 4; nn++) {
            float x2 = leaky(acc[pp][nn] + b2[n0 + nq * 4 + nn]);
            if (p < 31) psum[nn] += x2;
        }
    }
    #pragma unroll
    for (int nn = 0; nn < 4; nn++) red[pq][nq * 4 + nn] = psum[nn];
    __syncthreads();
    if (tid < 64) {
        float s = 0.f;
        #pragma unroll
        for (int pg = 0; pg < 8; pg++) s += red[pg][tid];
        g_CTX[i * FEAT + n0 + tid] = s;
    }
}

// ---------------------------------------------------------------------------
// Kernel 3: context1 = CTX/31; w = context1^4; Wt[f][i]=w; WS2t[f][i]=2*w*s;
//           A[i] = sum_f w*s^2.   grid 32, block 256.
// ---------------------------------------------------------------------------
__global__ void prep_kernel(const float* __restrict__ S) {
    __shared__ float rs[256];
    int i = blockIdx.x;
    int tid = threadIdx.x;
    float asum = 0.f;
    for (int f = tid; f < FEAT; f += 256) {
        float ctx = g_CTX[i * FEAT + f] * (1.0f / 31.0f);
        float c2 = ctx * ctx;
        float w = c2 * c2;
        float s = S[i * FEAT + f];
        g_Wt[f * WAY + i] = w;
        g_WS2t[f * WAY + i] = 2.0f * w * s;
        asum = fmaf(w, s * s, asum);
    }
    rs[tid] = asum;
    __syncthreads();
    for (int st = 128; st > 0; st >>= 1) {
        if (tid < st) rs[tid] += rs[tid + st];
        __syncthreads();
    }
    if (tid == 0) g_A[i] = rs[0];
}

// ---------------------------------------------------------------------------
// Kernel 4: out[j,i] = -sqrt(A[i] + sum_f q*(w*q - ws2))
// grid 128 (q-tiles of 32), block 128. Thread tile: 2q x 4i, K-tiles of 64.
// ---------------------------------------------------------------------------
__global__ void dist_kernel(const float* __restrict__ Q, float* __restrict__ out) {
    __shared__ float Qs[64 * 36];   // [kk][q]
    __shared__ float Ws[64 * 32];   // [kk][i]
    __shared__ float Ss[64 * 32];   // [kk][i]

    int jb = blockIdx.x * 32;
    int tid = threadIdx.x;
    int qg = tid >> 3;   // 0..15  -> queries qg*2 .. qg*2+1
    int ig = tid & 7;    // 0..7   -> classes ig*4 .. ig*4+3

    float acc[2][4];
    #pragma unroll
    for (int a = 0; a < 2; a++)
        #pragma unroll
        for (int b = 0; b < 4; b++) acc[a][b] = 0.f;

    for (int k0 = 0; k0 < FEAT; k0 += 64) {
        #pragma unroll
        for (int r = 0; r < 16; r++) {
            int idx = r * 128 + tid;      // 32q x 64k
            int q  = idx >> 6;
            int kk = idx & 63;
            Qs[kk * 36 + q] = Q[(jb + q) * FEAT + k0 + kk];
        }
        #pragma unroll
        for (int r = 0; r < 16; r++) {
            int idx = r * 128 + tid;      // 64k x 32i (flat, contiguous)
            Ws[idx] = g_Wt[k0 * WAY + idx];
            Ss[idx] = g_WS2t[k0 * WAY + idx];
        }
        __syncthreads();
        #pragma unroll 8
        for (int kk = 0; kk < 64; kk++) {
            float q0 = Qs[kk * 36 + qg * 2 + 0];
            float q1 = Qs[kk * 36 + qg * 2 + 1];
            float4 w  = *(const float4*)&Ws[kk * 32 + ig * 4];
            float4 s2 = *(const float4*)&Ss[kk * 32 + ig * 4];
            float t;
            t = fmaf(w.x, q0, -s2.x); acc[0][0] = fmaf(q0, t, acc[0][0]);
            t = fmaf(w.y, q0, -s2.y); acc[0][1] = fmaf(q0, t, acc[0][1]);
            t = fmaf(w.z, q0, -s2.z); acc[0][2] = fmaf(q0, t, acc[0][2]);
            t = fmaf(w.w, q0, -s2.w); acc[0][3] = fmaf(q0, t, acc[0][3]);
            t = fmaf(w.x, q1, -s2.x); acc[1][0] = fmaf(q1, t, acc[1][0]);
            t = fmaf(w.y, q1, -s2.y); acc[1][1] = fmaf(q1, t, acc[1][1]);
            t = fmaf(w.z, q1, -s2.z); acc[1][2] = fmaf(q1, t, acc[1][2]);
            t = fmaf(w.w, q1, -s2.w); acc[1][3] = fmaf(q1, t, acc[1][3]);
        }
        __syncthreads();
    }

    float a0 = g_A[ig * 4 + 0];
    float a1 = g_A[ig * 4 + 1];
    float a2 = g_A[ig * 4 + 2];
    float a3 = g_A[ig * 4 + 3];
    #pragma unroll
    for (int qq = 0; qq < 2; qq++) {
        int j = jb + qg * 2 + qq;
        float4 o;
        o.x = -sqrtf(fmaxf(a0 + acc[qq][0], 0.f));
        o.y = -sqrtf(fmaxf(a1 + acc[qq][1], 0.f));
        o.z = -sqrtf(fmaxf(a2 + acc[qq][2], 0.f));
        o.w = -sqrtf(fmaxf(a3 + acc[qq][3], 0.f));
        *(float4*)&out[j * WAY + ig * 4] = o;
    }
}

// ---------------------------------------------------------------------------
extern "C" void kernel_launch(void* const* d_in, const int* in_sizes, int n_in,
                              void* d_out, int out_size) {
    const float* S  = (const float*)d_in[0];  // [32, 640]
    const float* Q  = (const float*)d_in[1];  // [32, 128, 640]
    const float* W1 = (const float*)d_in[2];  // [640, 1280]
    const float* b1 = (const float*)d_in[3];  // [640]
    const float* W2 = (const float*)d_in[4];  // [640, 640]
    const float* b2 = (const float*)d_in[5];  // [640]
    float* out = (float*)d_out;               // [4096, 32]

    uv_kernel<<<160, 256>>>(S, W1);
    dim3 g2(FEAT / 64, WAY);
    gemm2_kernel<<<g2, 128>>>(W2, b1, b2);
    prep_kernel<<<WAY, 256>>>(S);
    dist_kernel<<<NQ / 32, 128>>>(Q, out);
}

// round 3
// speedup vs baseline: 1.1873x; 1.1873x over previous
#include <cuda_runtime.h>
#include <math.h>

#define WAY  32
#define QRY  128
#define FEAT 640
#define NQ   (WAY*QRY)      // 4096
#define KSPLIT 4
#define KSEG  (FEAT/KSPLIT) // 160

// Scratch (device globals; no allocation allowed)
__device__ __align__(16) float g_U[WAY*FEAT];
__device__ __align__(16) float g_V[WAY*FEAT];
__device__ __align__(16) float g_CTX[WAY*FEAT];
__device__ __align__(16) float g_Wt[FEAT*WAY];    // w[f][i] = context1^4, f-major
__device__ __align__(16) float g_WS2t[FEAT*WAY];  // 2*w*s,  f-major
__device__ __align__(16) float g_A[WAY];          // sum_f w*s^2
__device__ __align__(16) float g_P[KSPLIT][NQ*WAY]; // distance partials

__device__ __forceinline__ float leaky(float x) { return x > 0.f ? x : 0.2f * x; }

// ---------------------------------------------------------------------------
// Kernel 1: U = S @ W1[:, :640]^T, V = S @ W1[:, 640:]^T   (both [32,640])
// grid 160, block 256. Each warp: one output column c, 32 classes (one/lane).
// ---------------------------------------------------------------------------
__global__ void uv_kernel(const float* __restrict__ S, const float* __restrict__ W1) {
    __shared__ float St[320 * 33];
    int tid = threadIdx.x;
    int c = blockIdx.x * 8 + (tid >> 5);   // combined output column 0..1279
    int i = tid & 31;                      // class
    int half = (c >= FEAT) ? 1 : 0;
    int o = c - half * FEAT;
    const float* w1row = W1 + o * (2 * FEAT) + half * FEAT;

    float a0 = 0.f, a1 = 0.f, a2 = 0.f, a3 = 0.f;
    for (int k0 = 0; k0 < FEAT; k0 += 320) {
        __syncthreads();
        // Stage S[:, k0:k0+320] transposed, float4 gmem loads.
        #pragma unroll
        for (int r = 0; r < 10; r++) {
            int idx4 = r * 256 + tid;          // 2560 float4
            int ii = idx4 / 80;
            int kk4 = (idx4 - ii * 80) * 4;
            float4 v = *(const float4*)&S[ii * FEAT + k0 + kk4];
            St[(kk4 + 0) * 33 + ii] = v.x;
            St[(kk4 + 1) * 33 + ii] = v.y;
            St[(kk4 + 2) * 33 + ii] = v.z;
            St[(kk4 + 3) * 33 + ii] = v.w;
        }
        __syncthreads();
        #pragma unroll 4
        for (int kk = 0; kk < 320; kk += 4) {
            float4 wv = *(const float4*)&w1row[k0 + kk];
            a0 = fmaf(St[(kk + 0) * 33 + i], wv.x, a0);
            a1 = fmaf(St[(kk + 1) * 33 + i], wv.y, a1);
            a2 = fmaf(St[(kk + 2) * 33 + i], wv.z, a2);
            a3 = fmaf(St[(kk + 3) * 33 + i], wv.w, a3);
        }
    }
    float acc = (a0 + a1) + (a2 + a3);
    if (half) g_V[i * FEAT + o] = acc;
    else      g_U[i * FEAT + o] = acc;
}

// ---------------------------------------------------------------------------
// Kernel 2: per class i:  x1[p,k] = leaky(U[i,k] + V[j(p),k] + b1[k])  (p<31)
//           x2[p,n] = leaky(sum_k x1[p,k]*W2[n,k] + b2[n]); CTX[i,n] = sum_p x2
// grid (10 ntiles, 32 classes), block 64. Tile 32p x 64n, K-tiles 64.
// Thread tile 4p x 8n (two float4 n-halves) -> 1.5 B LDS per FMA.
// ---------------------------------------------------------------------------
__global__ void __launch_bounds__(64) gemm2_kernel(const float* __restrict__ W2,
                                                   const float* __restrict__ b1,
                                                   const float* __restrict__ b2) {
    __shared__ float X1s[64 * 36];   // [kk][p], float4-aligned rows
    __shared__ float W2s[64 * 68];   // [kk][n], float4-aligned rows

    int i  = blockIdx.y;
    int n0 = blockIdx.x * 64;
    int tid = threadIdx.x;
    int tp = tid >> 3;    // 0..7  -> p = tp*4
    int tn = tid & 7;     // 0..7  -> n in {tn*4..+3} u {32+tn*4..+3}

    float acc[4][8];
    #pragma unroll
    for (int a = 0; a < 4; a++)
        #pragma unroll
        for (int b = 0; b < 8; b++) acc[a][b] = 0.f;

    for (int k0 = 0; k0 < FEAT; k0 += 64) {
        __syncthreads();
        // Build X1 tile (32p x 64k) with float4 gmem loads.
        #pragma unroll
        for (int r = 0; r < 8; r++) {
            int idx4 = r * 64 + tid;          // 512 float4 = 2048 elems
            int p   = idx4 >> 4;
            int kk4 = (idx4 & 15) * 4;
            float4 v;
            if (p < 31) {
                int j = (p < i) ? p : p + 1;
                float4 u4 = *(const float4*)&g_U[i * FEAT + k0 + kk4];
                float4 v4 = *(const float4*)&g_V[j * FEAT + k0 + kk4];
                float4 b4 = *(const float4*)&b1[k0 + kk4];
                v.x = leaky(u4.x + v4.x + b4.x);
                v.y = leaky(u4.y + v4.y + b4.y);
                v.z = leaky(u4.z + v4.z + b4.z);
                v.w = leaky(u4.w + v4.w + b4.w);
            } else v = make_float4(0.f, 0.f, 0.f, 0.f);
            X1s[(kk4 + 0) * 36 + p] = v.x;
            X1s[(kk4 + 1) * 36 + p] = v.y;
            X1s[(kk4 + 2) * 36 + p] = v.z;
            X1s[(kk4 + 3) * 36 + p] = v.w;
        }
        // Load W2 tile (64n x 64k) transposed, float4 gmem loads.
        #pragma unroll
        for (int r = 0; r < 16; r++) {
            int idx4 = r * 64 + tid;          // 1024 float4 = 4096 elems
            int n   = idx4 >> 4;
            int kk4 = (idx4 & 15) * 4;
            float4 v = *(const float4*)&W2[(n0 + n) * FEAT + k0 + kk4];
            W2s[(kk4 + 0) * 68 + n] = v.x;
            W2s[(kk4 + 1) * 68 + n] = v.y;
            W2s[(kk4 + 2) * 68 + n] = v.z;
            W2s[(kk4 + 3) * 68 + n] = v.w;
        }
        __syncthreads();
        #pragma unroll 4
        for (int kk = 0; kk < 64; kk++) {
            float4 xv = *(const float4*)&X1s[kk * 36 + tp * 4];
            float4 w0 = *(const float4*)&W2s[kk * 68 + tn * 4];
            float4 w1 = *(const float4*)&W2s[kk * 68 + 32 + tn * 4];
            float xs[4] = {xv.x, xv.y, xv.z, xv.w};
            #pragma unroll
            for (int pp = 0; pp < 4; pp++) {
                acc[pp][0] = fmaf(xs[pp], w0.x, acc[pp][0]);
                acc[pp][1] = fmaf(xs[pp], w0.y, acc[pp][1]);
                acc[pp][2] = fmaf(xs[pp], w0.z, acc[pp][2]);
                acc[pp][3] = fmaf(xs[pp], w0.w, acc[pp][3]);
                acc[pp][4] = fmaf(xs[pp], w1.x, acc[pp][4]);
                acc[pp][5] = fmaf(xs[pp], w1.y, acc[pp][5]);
                acc[pp][6] = fmaf(xs[pp], w1.z, acc[pp][6]);
                acc[pp][7] = fmaf(xs[pp], w1.w, acc[pp][7]);
            }
        }
    }

    // Epilogue: x2 = leaky(acc + b2), sum over valid pairs p<31.
    float psum[8] = {0.f,0.f,0.f,0.f,0.f,0.f,0.f,0.f};
    #pragma unroll
    for (int pp = 0; pp < 4; pp++) {
        int p = tp * 4 + pp;
        if (p < 31) {
            #pragma unroll
            for (int nn = 0; nn < 8; nn++) {
                int col = (nn < 4) ? (tn * 4 + nn) : (32 + tn * 4 + (nn - 4));
                psum[nn] += leaky(acc[pp][nn] + b2[n0 + col]);
            }
        }
    }
    __syncthreads();                 // X1s reuse as reduction buffer
    float* red = X1s;                // red[8][64]
    #pragma unroll
    for (int nn = 0; nn < 8; nn++) {
        int col = (nn < 4) ? (tn * 4 + nn) : (32 + tn * 4 + (nn - 4));
        red[tp * 64 + col] = psum[nn];
    }
    __syncthreads();
    if (tid < 64) {
        float s = 0.f;
        #pragma unroll
        for (int g = 0; g < 8; g++) s += red[g * 64 + tid];
        g_CTX[i * FEAT + n0 + tid] = s;
    }
}

// ---------------------------------------------------------------------------
// Kernel 3: context1 = CTX/31; w = context1^4; Wt[f][i]=w; WS2t[f][i]=2*w*s;
//           A[i] = sum_f w*s^2.   grid 32, block 256.
// ---------------------------------------------------------------------------
__global__ void prep_kernel(const float* __restrict__ S) {
    __shared__ float rs[256];
    int i = blockIdx.x;
    int tid = threadIdx.x;
    float asum = 0.f;
    for (int f = tid; f < FEAT; f += 256) {
        float ctx = g_CTX[i * FEAT + f] * (1.0f / 31.0f);
        float c2 = ctx * ctx;
        float w = c2 * c2;
        float s = S[i * FEAT + f];
        g_Wt[f * WAY + i] = w;
        g_WS2t[f * WAY + i] = 2.0f * w * s;
        asum = fmaf(w, s * s, asum);
    }
    rs[tid] = asum;
    __syncthreads();
    for (int st = 128; st > 0; st >>= 1) {
        if (tid < st) rs[tid] += rs[tid + st];
        __syncthreads();
    }
    if (tid == 0) g_A[i] = rs[0];
}

// ---------------------------------------------------------------------------
// Kernel 4: dist partials. grid (64 q-tiles, 4 k-splits), block 128.
// Block tile 64q x 32i x 160k; thread tile 4q x 4i; k-subtiles of 32.
// P[ks][j*32+i] = sum_{f in seg} q*(w*q - ws2)
// ---------------------------------------------------------------------------
__global__ void __launch_bounds__(128) dist_partial(const float* __restrict__ Q) {
    __shared__ float Qs[32 * 68];   // [kk][q], float4-aligned rows
    __shared__ float Ws[32 * 32];   // [kk][i]
    __shared__ float Ss[32 * 32];   // [kk][i]

    int jb = blockIdx.x * 64;
    int ks = blockIdx.y;
    int kbase = ks * KSEG;
    int tid = threadIdx.x;
    int tq = tid >> 3;   // 0..15 -> q = tq*4
    int ti = tid & 7;    // 0..7  -> i = ti*4

    float acc[4][4];
    #pragma unroll
    for (int a = 0; a < 4; a++)
        #pragma unroll
        for (int b = 0; b < 4; b++) acc[a][b] = 0.f;

    for (int kt = 0; kt < KSEG; kt += 32) {
        int k0 = kbase + kt;
        __syncthreads();
        // Stage Q (64q x 32k), float4 loads.
        #pragma unroll
        for (int r = 0; r < 4; r++) {
            int idx4 = r * 128 + tid;      // 512 float4
            int q   = idx4 >> 3;
            int kk4 = (idx4 & 7) * 4;
            float4 v = *(const float4*)&Q[(jb + q) * FEAT + k0 + kk4];
            Qs[(kk4 + 0) * 68 + q] = v.x;
            Qs[(kk4 + 1) * 68 + q] = v.y;
            Qs[(kk4 + 2) * 68 + q] = v.z;
            Qs[(kk4 + 3) * 68 + q] = v.w;
        }
        // Stage w / ws2 (32k x 32i, already f-major -> flat copy).
        #pragma unroll
        for (int r = 0; r < 2; r++) {
            int idx4 = r * 128 + tid;      // 256 float4 each
            *(float4*)&Ws[idx4 * 4] = *(const float4*)&g_Wt[k0 * WAY + idx4 * 4];
            *(float4*)&Ss[idx4 * 4] = *(const float4*)&g_WS2t[k0 * WAY + idx4 * 4];
        }
        __syncthreads();
        #pragma unroll 4
        for (int kk = 0; kk < 32; kk++) {
            float4 qv = *(const float4*)&Qs[kk * 68 + tq * 4];
            float4 w  = *(const float4*)&Ws[kk * 32 + ti * 4];
            float4 s2 = *(const float4*)&Ss[kk * 32 + ti * 4];
            float qs[4] = {qv.x, qv.y, qv.z, qv.w};
            #pragma unroll
            for (int qq = 0; qq < 4; qq++) {
                float t;
                t = fmaf(w.x, qs[qq], -s2.x); acc[qq][0] = fmaf(qs[qq], t, acc[qq][0]);
                t = fmaf(w.y, qs[qq], -s2.y); acc[qq][1] = fmaf(qs[qq], t, acc[qq][1]);
                t = fmaf(w.z, qs[qq], -s2.z); acc[qq][2] = fmaf(qs[qq], t, acc[qq][2]);
                t = fmaf(w.w, qs[qq], -s2.w); acc[qq][3] = fmaf(qs[qq], t, acc[qq][3]);
            }
        }
    }

    float* P = g_P[ks];
    #pragma unroll
    for (int qq = 0; qq < 4; qq++) {
        int j = jb + tq * 4 + qq;
        *(float4*)&P[j * WAY + ti * 4] =
            make_float4(acc[qq][0], acc[qq][1], acc[qq][2], acc[qq][3]);
    }
}

// ---------------------------------------------------------------------------
// Kernel 5: out[j,i] = -sqrt(max(A[i] + sum_ks P[ks][j,i], 0))
// grid 128, block 256, float4 per thread.
// ---------------------------------------------------------------------------
__global__ void finalize_kernel(float* __restrict__ out) {
    int gid = blockIdx.x * 256 + threadIdx.x;
    int base = gid * 4;
    float4 s = *(const float4*)&g_P[0][base];
    #pragma unroll
    for (int ks = 1; ks < KSPLIT; ks++) {
        float4 p = *(const float4*)&g_P[ks][base];
        s.x += p.x; s.y += p.y; s.z += p.z; s.w += p.w;
    }
    int i = base & 31;
    float4 a = *(const float4*)&g_A[i];
    float4 o;
    o.x = -sqrtf(fmaxf(a.x + s.x, 0.f));
    o.y = -sqrtf(fmaxf(a.y + s.y, 0.f));
    o.z = -sqrtf(fmaxf(a.z + s.z, 0.f));
    o.w = -sqrtf(fmaxf(a.w + s.w, 0.f));
    *(float4*)&out[base] = o;
}

// ---------------------------------------------------------------------------
extern "C" void kernel_launch(void* const* d_in, const int* in_sizes, int n_in,
                              void* d_out, int out_size) {
    const float* S  = (const float*)d_in[0];  // [32, 640]
    const float* Q  = (const float*)d_in[1];  // [32, 128, 640]
    const float* W1 = (const float*)d_in[2];  // [640, 1280]
    const float* b1 = (const float*)d_in[3];  // [640]
    const float* W2 = (const float*)d_in[4];  // [640, 640]
    const float* b2 = (const float*)d_in[5];  // [640]
    float* out = (float*)d_out;               // [4096, 32]

    uv_kernel<<<160, 256>>>(S, W1);
    gemm2_kernel<<<dim3(FEAT / 64, WAY), 64>>>(W2, b1, b2);
    prep_kernel<<<WAY, 256>>>(S);
    dist_partial<<<dim3(NQ / 64, KSPLIT), 128>>>(Q);
    finalize_kernel<<<NQ * WAY / (256 * 4), 256>>>(out);
}

// round 4
// speedup vs baseline: 1.3006x; 1.0954x over previous
#include <cuda_runtime.h>
#include <math.h>

#define WAY  32
#define QRY  128
#define FEAT 640
#define NQ   (WAY*QRY)      // 4096
#define NPAIR (WAY*(WAY-1)) // 992
#define MPAD 1024           // padded M for gemm2

#define KSPLIT 8            // dist k-split
#define KSEG   (FEAT/KSPLIT)   // 80

#define KS2    4            // gemm2 k-split
#define KSEG2  (FEAT/KS2)   // 160

// Scratch (device globals; no allocation allowed)
__device__ __align__(16) float g_U[WAY*FEAT];
__device__ __align__(16) float g_V[WAY*FEAT];
__device__ __align__(16) float g_CTX[WAY*FEAT];
__device__ __align__(16) float g_Wt[FEAT*WAY];    // w[f][i] = context1^4, f-major
__device__ __align__(16) float g_WS2t[FEAT*WAY];  // 2*w*s,  f-major
__device__ __align__(16) float g_A[WAY];          // sum_f w*s^2
__device__ __align__(16) float g_P[KSPLIT][NQ*WAY];     // distance partials (4 MB)
__device__ __align__(16) float g_P2[KS2][NPAIR*FEAT];   // gemm2 partials (10.2 MB)

__device__ __forceinline__ float leaky(float x) { return x > 0.f ? x : 0.2f * x; }

// ---------------------------------------------------------------------------
// Kernel 1: U = S @ W1[:, :640]^T, V = S @ W1[:, 640:]^T   (both [32,640])
// grid 160, block 256. Each warp: one output column c, 32 classes (one/lane).
// ---------------------------------------------------------------------------
__global__ void uv_kernel(const float* __restrict__ S, const float* __restrict__ W1) {
    __shared__ float St[320 * 33];
    int tid = threadIdx.x;
    int c = blockIdx.x * 8 + (tid >> 5);   // combined output column 0..1279
    int i = tid & 31;                      // class
    int half = (c >= FEAT) ? 1 : 0;
    int o = c - half * FEAT;
    const float* w1row = W1 + o * (2 * FEAT) + half * FEAT;

    float a0 = 0.f, a1 = 0.f, a2 = 0.f, a3 = 0.f;
    for (int k0 = 0; k0 < FEAT; k0 += 320) {
        __syncthreads();
        #pragma unroll
        for (int r = 0; r < 10; r++) {
            int idx4 = r * 256 + tid;          // 2560 float4
            int ii = idx4 / 80;
            int kk4 = (idx4 - ii * 80) * 4;
            float4 v = *(const float4*)&S[ii * FEAT + k0 + kk4];
            St[(kk4 + 0) * 33 + ii] = v.x;
            St[(kk4 + 1) * 33 + ii] = v.y;
            St[(kk4 + 2) * 33 + ii] = v.z;
            St[(kk4 + 3) * 33 + ii] = v.w;
        }
        __syncthreads();
        #pragma unroll 4
        for (int kk = 0; kk < 320; kk += 4) {
            float4 wv = *(const float4*)&w1row[k0 + kk];
            a0 = fmaf(St[(kk + 0) * 33 + i], wv.x, a0);
            a1 = fmaf(St[(kk + 1) * 33 + i], wv.y, a1);
            a2 = fmaf(St[(kk + 2) * 33 + i], wv.z, a2);
            a3 = fmaf(St[(kk + 3) * 33 + i], wv.w, a3);
        }
    }
    float acc = (a0 + a1) + (a2 + a3);
    if (half) g_V[i * FEAT + o] = acc;
    else      g_U[i * FEAT + o] = acc;
}

// ---------------------------------------------------------------------------
// Kernel 2a: flat GEMM partials. X1[r,k] = leaky(U[i,k]+V[j,k]+b1[k]),
//   r = i*31+p, j = p<i?p:p+1.  P2[ks][r][n] = sum_{k in seg} X1[r,k]*W2[n,k]
// grid (16 m-tiles, 10 n-tiles, KS2), block 256. Tile 64m x 64n, k-subtile 32.
// Thread tile 4m x 4n.
// ---------------------------------------------------------------------------
__global__ void __launch_bounds__(256) gemm2_partial(const float* __restrict__ W2,
                                                     const float* __restrict__ b1) {
    __shared__ float Xs[32 * 68];   // [kk][m]
    __shared__ float Ws[32 * 68];   // [kk][n]

    int m0 = blockIdx.x * 64;
    int n0 = blockIdx.y * 64;
    int ks = blockIdx.z;
    int kbase = ks * KSEG2;
    int tid = threadIdx.x;
    int tm = tid >> 4;    // 0..15 -> m = tm*4
    int tn = tid & 15;    // 0..15 -> n = tn*4

    float acc[4][4];
    #pragma unroll
    for (int a = 0; a < 4; a++)
        #pragma unroll
        for (int b = 0; b < 4; b++) acc[a][b] = 0.f;

    for (int kt = 0; kt < KSEG2; kt += 32) {
        int k0 = kbase + kt;
        __syncthreads();
        // Stage X1 tile (64m x 32k): 512 float4, 2 per thread.
        #pragma unroll
        for (int rr = 0; rr < 2; rr++) {
            int idx4 = rr * 256 + tid;
            int rl  = idx4 >> 3;
            int kk4 = (idx4 & 7) * 4;
            int r = m0 + rl;
            float4 v;
            if (r < NPAIR) {
                int i = r / 31;
                int p = r - i * 31;
                int j = (p < i) ? p : p + 1;
                float4 u4 = *(const float4*)&g_U[i * FEAT + k0 + kk4];
                float4 v4 = *(const float4*)&g_V[j * FEAT + k0 + kk4];
                float4 b4 = *(const float4*)&b1[k0 + kk4];
                v.x = leaky(u4.x + v4.x + b4.x);
                v.y = leaky(u4.y + v4.y + b4.y);
                v.z = leaky(u4.z + v4.z + b4.z);
                v.w = leaky(u4.w + v4.w + b4.w);
            } else v = make_float4(0.f, 0.f, 0.f, 0.f);
            Xs[(kk4 + 0) * 68 + rl] = v.x;
            Xs[(kk4 + 1) * 68 + rl] = v.y;
            Xs[(kk4 + 2) * 68 + rl] = v.z;
            Xs[(kk4 + 3) * 68 + rl] = v.w;
        }
        // Stage W2 tile (64n x 32k) transposed.
        #pragma unroll
        for (int rr = 0; rr < 2; rr++) {
            int idx4 = rr * 256 + tid;
            int nl  = idx4 >> 3;
            int kk4 = (idx4 & 7) * 4;
            float4 v = *(const float4*)&W2[(n0 + nl) * FEAT + k0 + kk4];
            Ws[(kk4 + 0) * 68 + nl] = v.x;
            Ws[(kk4 + 1) * 68 + nl] = v.y;
            Ws[(kk4 + 2) * 68 + nl] = v.z;
            Ws[(kk4 + 3) * 68 + nl] = v.w;
        }
        __syncthreads();
        #pragma unroll 8
        for (int kk = 0; kk < 32; kk++) {
            float4 xv = *(const float4*)&Xs[kk * 68 + tm * 4];
            float4 wv = *(const float4*)&Ws[kk * 68 + tn * 4];
            float xs[4] = {xv.x, xv.y, xv.z, xv.w};
            #pragma unroll
            for (int mm = 0; mm < 4; mm++) {
                acc[mm][0] = fmaf(xs[mm], wv.x, acc[mm][0]);
                acc[mm][1] = fmaf(xs[mm], wv.y, acc[mm][1]);
                acc[mm][2] = fmaf(xs[mm], wv.z, acc[mm][2]);
                acc[mm][3] = fmaf(xs[mm], wv.w, acc[mm][3]);
            }
        }
    }

    float* P = g_P2[ks];
    #pragma unroll
    for (int mm = 0; mm < 4; mm++) {
        int r = m0 + tm * 4 + mm;
        if (r < NPAIR)
            *(float4*)&P[r * FEAT + n0 + tn * 4] =
                make_float4(acc[mm][0], acc[mm][1], acc[mm][2], acc[mm][3]);
    }
}

// ---------------------------------------------------------------------------
// Kernel 2b: CTX[i,n] = sum_{p<31} leaky(sum_ks P2[ks][i*31+p][n] + b2[n])
// grid (10 ntiles, 32 classes), block 64.
// ---------------------------------------------------------------------------
__global__ void gemm2_reduce(const float* __restrict__ b2) {
    int n = blockIdx.x * 64 + threadIdx.x;
    int i = blockIdx.y;
    float bb = b2[n];
    float s = 0.f;
    #pragma unroll 4
    for (int p = 0; p < 31; p++) {
        int r = i * 31 + p;
        float v = g_P2[0][r * FEAT + n];
        #pragma unroll
        for (int ks = 1; ks < KS2; ks++) v += g_P2[ks][r * FEAT + n];
        s += leaky(v + bb);
    }
    g_CTX[i * FEAT + n] = s;
}

// ---------------------------------------------------------------------------
// Kernel 3: context1 = CTX/31; w = context1^4; Wt[f][i]=w; WS2t[f][i]=2*w*s;
//           A[i] = sum_f w*s^2.   grid 32, block 256.
// ---------------------------------------------------------------------------
__global__ void prep_kernel(const float* __restrict__ S) {
    __shared__ float rs[256];
    int i = blockIdx.x;
    int tid = threadIdx.x;
    float asum = 0.f;
    for (int f = tid; f < FEAT; f += 256) {
        float ctx = g_CTX[i * FEAT + f] * (1.0f / 31.0f);
        float c2 = ctx * ctx;
        float w = c2 * c2;
        float s = S[i * FEAT + f];
        g_Wt[f * WAY + i] = w;
        g_WS2t[f * WAY + i] = 2.0f * w * s;
        asum = fmaf(w, s * s, asum);
    }
    rs[tid] = asum;
    __syncthreads();
    for (int st = 128; st > 0; st >>= 1) {
        if (tid < st) rs[tid] += rs[tid + st];
        __syncthreads();
    }
    if (tid == 0) g_A[i] = rs[0];
}

// ---------------------------------------------------------------------------
// Kernel 4: dist partials. grid (64 q-tiles, KSPLIT=8), block 128.
// Block tile 64q x 32i x 80k; thread tile 4q x 4i; k-subtiles of 16.
// ---------------------------------------------------------------------------
__global__ void __launch_bounds__(128) dist_partial(const float* __restrict__ Q) {
    __shared__ float Qs[16 * 68];   // [kk][q]
    __shared__ float Ws[16 * 32];   // [kk][i]
    __shared__ float Ss[16 * 32];   // [kk][i]

    int jb = blockIdx.x * 64;
    int ks = blockIdx.y;
    int kbase = ks * KSEG;
    int tid = threadIdx.x;
    int tq = tid >> 3;   // 0..15 -> q = tq*4
    int ti = tid & 7;    // 0..7  -> i = ti*4

    float acc[4][4];
    #pragma unroll
    for (int a = 0; a < 4; a++)
        #pragma unroll
        for (int b = 0; b < 4; b++) acc[a][b] = 0.f;

    for (int kt = 0; kt < KSEG; kt += 16) {
        int k0 = kbase + kt;
        __syncthreads();
        // Stage Q (64q x 16k): 256 float4, 2 per thread.
        #pragma unroll
        for (int r = 0; r < 2; r++) {
            int idx4 = r * 128 + tid;
            int q   = idx4 >> 2;
            int kk4 = (idx4 & 3) * 4;
            float4 v = *(const float4*)&Q[(jb + q) * FEAT + k0 + kk4];
            Qs[(kk4 + 0) * 68 + q] = v.x;
            Qs[(kk4 + 1) * 68 + q] = v.y;
            Qs[(kk4 + 2) * 68 + q] = v.z;
            Qs[(kk4 + 3) * 68 + q] = v.w;
        }
        // Stage w / ws2 (16k x 32i, f-major flat): 128 float4 each, 1/thread.
        *(float4*)&Ws[tid * 4] = *(const float4*)&g_Wt[k0 * WAY + tid * 4];
        *(float4*)&Ss[tid * 4] = *(const float4*)&g_WS2t[k0 * WAY + tid * 4];
        __syncthreads();
        #pragma unroll
        for (int kk = 0; kk < 16; kk++) {
            float4 qv = *(const float4*)&Qs[kk * 68 + tq * 4];
            float4 w  = *(const float4*)&Ws[kk * 32 + ti * 4];
            float4 s2 = *(const float4*)&Ss[kk * 32 + ti * 4];
            float qs[4] = {qv.x, qv.y, qv.z, qv.w};
            #pragma unroll
            for (int qq = 0; qq < 4; qq++) {
                float t;
                t = fmaf(w.x, qs[qq], -s2.x); acc[qq][0] = fmaf(qs[qq], t, acc[qq][0]);
                t = fmaf(w.y, qs[qq], -s2.y); acc[qq][1] = fmaf(qs[qq], t, acc[qq][1]);
                t = fmaf(w.z, qs[qq], -s2.z); acc[qq][2] = fmaf(qs[qq], t, acc[qq][2]);
                t = fmaf(w.w, qs[qq], -s2.w); acc[qq][3] = fmaf(qs[qq], t, acc[qq][3]);
            }
        }
    }

    float* P = g_P[ks];
    #pragma unroll
    for (int qq = 0; qq < 4; qq++) {
        int j = jb + tq * 4 + qq;
        *(float4*)&P[j * WAY + ti * 4] =
            make_float4(acc[qq][0], acc[qq][1], acc[qq][2], acc[qq][3]);
    }
}

// ---------------------------------------------------------------------------
// Kernel 5: out[j,i] = -sqrt(max(A[i] + sum_ks P[ks][j,i], 0))
// grid 128, block 256, float4 per thread.
// ---------------------------------------------------------------------------
__global__ void finalize_kernel(float* __restrict__ out) {
    int gid = blockIdx.x * 256 + threadIdx.x;
    int base = gid * 4;
    float4 s = *(const float4*)&g_P[0][base];
    #pragma unroll
    for (int ks = 1; ks < KSPLIT; ks++) {
        float4 p = *(const float4*)&g_P[ks][base];
        s.x += p.x; s.y += p.y; s.z += p.z; s.w += p.w;
    }
    int i = base & 31;
    float4 a = *(const float4*)&g_A[i];
    float4 o;
    o.x = -sqrtf(fmaxf(a.x + s.x, 0.f));
    o.y = -sqrtf(fmaxf(a.y + s.y, 0.f));
    o.z = -sqrtf(fmaxf(a.z + s.z, 0.f));
    o.w = -sqrtf(fmaxf(a.w + s.w, 0.f));
    *(float4*)&out[base] = o;
}

// ---------------------------------------------------------------------------
extern "C" void kernel_launch(void* const* d_in, const int* in_sizes, int n_in,
                              void* d_out, int out_size) {
    const float* S  = (const float*)d_in[0];  // [32, 640]
    const float* Q  = (const float*)d_in[1];  // [32, 128, 640]
    const float* W1 = (const float*)d_in[2];  // [640, 1280]
    const float* b1 = (const float*)d_in[3];  // [640]
    const float* W2 = (const float*)d_in[4];  // [640, 640]
    const float* b2 = (const float*)d_in[5];  // [640]
    float* out = (float*)d_out;               // [4096, 32]

    uv_kernel<<<160, 256>>>(S, W1);
    gemm2_partial<<<dim3(MPAD / 64, FEAT / 64, KS2), 256>>>(W2, b1);
    gemm2_reduce<<<dim3(FEAT / 64, WAY), 64>>>(b2);
    prep_kernel<<<WAY, 256>>>(S);
    dist_partial<<<dim3(NQ / 64, KSPLIT), 128>>>(Q);
    finalize_kernel<<<NQ * WAY / (256 * 4), 256>>>(out);
}

// round 5
// speedup vs baseline: 1.3295x; 1.0222x over previous
#include <cuda_runtime.h>
#include <math.h>

#define WAY  32
#define QRY  128
#define FEAT 640
#define NQ   (WAY*QRY)      // 4096
#define NPAIR (WAY*(WAY-1)) // 992
#define MPAD 1024           // padded M for gemm2

#define KSPLIT 8            // dist k-split
#define KSEG   (FEAT/KSPLIT)   // 80

#define KS2    4            // gemm2 k-split
#define KSEG2  (FEAT/KS2)   // 160

#define NCHUNK 5            // ctx_prep n-chunks of 128

// Scratch (device globals; no allocation allowed)
__device__ __align__(16) float g_U[WAY*FEAT];
__device__ __align__(16) float g_V[WAY*FEAT];
__device__ __align__(16) float g_Wt[FEAT*WAY];    // w[f][i] = context1^4, f-major
__device__ __align__(16) float g_WS2t[FEAT*WAY];  // 2*w*s,  f-major
__device__ __align__(16) float g_Apart[NCHUNK][WAY]; // partials of sum_f w*s^2
__device__ __align__(16) float g_P[KSPLIT][NQ*WAY];     // distance partials (4 MB)
__device__ __align__(16) float g_P2[KS2][NPAIR*FEAT];   // gemm2 partials (10.2 MB)

__device__ __forceinline__ float leaky(float x) { return x > 0.f ? x : 0.2f * x; }

// ---------------------------------------------------------------------------
// Kernel 1: U = S @ W1[:, :640]^T, V = S @ W1[:, 640:]^T   (both [32,640])
// grid 160, block 256. Each warp: one output column c, 32 classes (one/lane).
// ---------------------------------------------------------------------------
__global__ void uv_kernel(const float* __restrict__ S, const float* __restrict__ W1) {
    __shared__ float St[320 * 33];
    int tid = threadIdx.x;
    int c = blockIdx.x * 8 + (tid >> 5);   // combined output column 0..1279
    int i = tid & 31;                      // class
    int half = (c >= FEAT) ? 1 : 0;
    int o = c - half * FEAT;
    const float* w1row = W1 + o * (2 * FEAT) + half * FEAT;

    float a0 = 0.f, a1 = 0.f, a2 = 0.f, a3 = 0.f;
    for (int k0 = 0; k0 < FEAT; k0 += 320) {
        __syncthreads();
        #pragma unroll
        for (int r = 0; r < 10; r++) {
            int idx4 = r * 256 + tid;          // 2560 float4
            int ii = idx4 / 80;
            int kk4 = (idx4 - ii * 80) * 4;
            float4 v = *(const float4*)&S[ii * FEAT + k0 + kk4];
            St[(kk4 + 0) * 33 + ii] = v.x;
            St[(kk4 + 1) * 33 + ii] = v.y;
            St[(kk4 + 2) * 33 + ii] = v.z;
            St[(kk4 + 3) * 33 + ii] = v.w;
        }
        __syncthreads();
        #pragma unroll 4
        for (int kk = 0; kk < 320; kk += 4) {
            float4 wv = *(const float4*)&w1row[k0 + kk];
            a0 = fmaf(St[(kk + 0) * 33 + i], wv.x, a0);
            a1 = fmaf(St[(kk + 1) * 33 + i], wv.y, a1);
            a2 = fmaf(St[(kk + 2) * 33 + i], wv.z, a2);
            a3 = fmaf(St[(kk + 3) * 33 + i], wv.w, a3);
        }
    }
    float acc = (a0 + a1) + (a2 + a3);
    if (half) g_V[i * FEAT + o] = acc;
    else      g_U[i * FEAT + o] = acc;
}

// ---------------------------------------------------------------------------
// Kernel 2: flat GEMM partials. X1[r,k] = leaky(U[i,k]+V[j,k]+b1[k]),
//   r = i*31+p, j = p<i?p:p+1.  P2[ks][r][n] = sum_{k in seg} X1[r,k]*W2[n,k]
// grid (16 m-tiles, 10 n-tiles, KS2), block 256. Tile 64m x 64n, k-subtile 32.
// Thread tile 4m x 4n.
// ---------------------------------------------------------------------------
__global__ void __launch_bounds__(256) gemm2_partial(const float* __restrict__ W2,
                                                     const float* __restrict__ b1) {
    __shared__ float Xs[32 * 68];   // [kk][m]
    __shared__ float Ws[32 * 68];   // [kk][n]

    int m0 = blockIdx.x * 64;
    int n0 = blockIdx.y * 64;
    int ks = blockIdx.z;
    int kbase = ks * KSEG2;
    int tid = threadIdx.x;
    int tm = tid >> 4;    // 0..15 -> m = tm*4
    int tn = tid & 15;    // 0..15 -> n = tn*4

    float acc[4][4];
    #pragma unroll
    for (int a = 0; a < 4; a++)
        #pragma unroll
        for (int b = 0; b < 4; b++) acc[a][b] = 0.f;

    for (int kt = 0; kt < KSEG2; kt += 32) {
        int k0 = kbase + kt;
        __syncthreads();
        // Stage X1 tile (64m x 32k): 512 float4, 2 per thread.
        #pragma unroll
        for (int rr = 0; rr < 2; rr++) {
            int idx4 = rr * 256 + tid;
            int rl  = idx4 >> 3;
            int kk4 = (idx4 & 7) * 4;
            int r = m0 + rl;
            float4 v;
            if (r < NPAIR) {
                int i = r / 31;
                int p = r - i * 31;
                int j = (p < i) ? p : p + 1;
                float4 u4 = *(const float4*)&g_U[i * FEAT + k0 + kk4];
                float4 v4 = *(const float4*)&g_V[j * FEAT + k0 + kk4];
                float4 b4 = *(const float4*)&b1[k0 + kk4];
                v.x = leaky(u4.x + v4.x + b4.x);
                v.y = leaky(u4.y + v4.y + b4.y);
                v.z = leaky(u4.z + v4.z + b4.z);
                v.w = leaky(u4.w + v4.w + b4.w);
            } else v = make_float4(0.f, 0.f, 0.f, 0.f);
            Xs[(kk4 + 0) * 68 + rl] = v.x;
            Xs[(kk4 + 1) * 68 + rl] = v.y;
            Xs[(kk4 + 2) * 68 + rl] = v.z;
            Xs[(kk4 + 3) * 68 + rl] = v.w;
        }
        // Stage W2 tile (64n x 32k) transposed.
        #pragma unroll
        for (int rr = 0; rr < 2; rr++) {
            int idx4 = rr * 256 + tid;
            int nl  = idx4 >> 3;
            int kk4 = (idx4 & 7) * 4;
            float4 v = *(const float4*)&W2[(n0 + nl) * FEAT + k0 + kk4];
            Ws[(kk4 + 0) * 68 + nl] = v.x;
            Ws[(kk4 + 1) * 68 + nl] = v.y;
            Ws[(kk4 + 2) * 68 + nl] = v.z;
            Ws[(kk4 + 3) * 68 + nl] = v.w;
        }
        __syncthreads();
        #pragma unroll 8
        for (int kk = 0; kk < 32; kk++) {
            float4 xv = *(const float4*)&Xs[kk * 68 + tm * 4];
            float4 wv = *(const float4*)&Ws[kk * 68 + tn * 4];
            float xs[4] = {xv.x, xv.y, xv.z, xv.w};
            #pragma unroll
            for (int mm = 0; mm < 4; mm++) {
                acc[mm][0] = fmaf(xs[mm], wv.x, acc[mm][0]);
                acc[mm][1] = fmaf(xs[mm], wv.y, acc[mm][1]);
                acc[mm][2] = fmaf(xs[mm], wv.z, acc[mm][2]);
                acc[mm][3] = fmaf(xs[mm], wv.w, acc[mm][3]);
            }
        }
    }

    float* P = g_P2[ks];
    #pragma unroll
    for (int mm = 0; mm < 4; mm++) {
        int r = m0 + tm * 4 + mm;
        if (r < NPAIR)
            *(float4*)&P[r * FEAT + n0 + tn * 4] =
                make_float4(acc[mm][0], acc[mm][1], acc[mm][2], acc[mm][3]);
    }
}

// ---------------------------------------------------------------------------
// Kernel 3 (fused reduce+prep): for class i, n = chunk*128 + tid:
//   ctx = (1/31) * sum_{p<31} leaky(sum_ks P2[ks][i*31+p][n] + b2[n])
//   w = ctx^4; Wt[n][i] = w; WS2t[n][i] = 2*w*s; Apart[chunk][i] = sum_n w*s^2
// grid (5 chunks, 32 classes), block 128.
// ---------------------------------------------------------------------------
__global__ void __launch_bounds__(128) ctx_prep_kernel(const float* __restrict__ S,
                                                       const float* __restrict__ b2) {
    __shared__ float rs[128];
    int i = blockIdx.y;
    int n = blockIdx.x * 128 + threadIdx.x;
    int tid = threadIdx.x;

    float bb = b2[n];
    float ssum = 0.f;
    int rbase = i * 31;
    #pragma unroll 4
    for (int p = 0; p < 31; p++) {
        int off = (rbase + p) * FEAT + n;
        float v = g_P2[0][off] + g_P2[1][off] + g_P2[2][off] + g_P2[3][off];
        ssum += leaky(v + bb);
    }
    float ctx = ssum * (1.0f / 31.0f);
    float c2 = ctx * ctx;
    float w = c2 * c2;
    float s = S[i * FEAT + n];
    g_Wt[n * WAY + i] = w;
    g_WS2t[n * WAY + i] = 2.0f * w * s;

    rs[tid] = w * s * s;
    __syncthreads();
    for (int st = 64; st > 0; st >>= 1) {
        if (tid < st) rs[tid] += rs[tid + st];
        __syncthreads();
    }
    if (tid == 0) g_Apart[blockIdx.x][i] = rs[0];
}

// ---------------------------------------------------------------------------
// Kernel 4: dist partials. grid (64 q-tiles, KSPLIT=8), block 128.
// Block tile 64q x 32i x 80k; thread tile 4q x 4i; k-subtiles of 16.
// ---------------------------------------------------------------------------
__global__ void __launch_bounds__(128) dist_partial(const float* __restrict__ Q) {
    __shared__ float Qs[16 * 68];   // [kk][q]
    __shared__ float Ws[16 * 32];   // [kk][i]
    __shared__ float Ss[16 * 32];   // [kk][i]

    int jb = blockIdx.x * 64;
    int ks = blockIdx.y;
    int kbase = ks * KSEG;
    int tid = threadIdx.x;
    int tq = tid >> 3;   // 0..15 -> q = tq*4
    int ti = tid & 7;    // 0..7  -> i = ti*4

    float acc[4][4];
    #pragma unroll
    for (int a = 0; a < 4; a++)
        #pragma unroll
        for (int b = 0; b < 4; b++) acc[a][b] = 0.f;

    for (int kt = 0; kt < KSEG; kt += 16) {
        int k0 = kbase + kt;
        __syncthreads();
        // Stage Q (64q x 16k): 256 float4, 2 per thread.
        #pragma unroll
        for (int r = 0; r < 2; r++) {
            int idx4 = r * 128 + tid;
            int q   = idx4 >> 2;
            int kk4 = (idx4 & 3) * 4;
            float4 v = *(const float4*)&Q[(jb + q) * FEAT + k0 + kk4];
            Qs[(kk4 + 0) * 68 + q] = v.x;
            Qs[(kk4 + 1) * 68 + q] = v.y;
            Qs[(kk4 + 2) * 68 + q] = v.z;
            Qs[(kk4 + 3) * 68 + q] = v.w;
        }
        // Stage w / ws2 (16k x 32i, f-major flat): 128 float4 each, 1/thread.
        *(float4*)&Ws[tid * 4] = *(const float4*)&g_Wt[k0 * WAY + tid * 4];
        *(float4*)&Ss[tid * 4] = *(const float4*)&g_WS2t[k0 * WAY + tid * 4];
        __syncthreads();
        #pragma unroll
        for (int kk = 0; kk < 16; kk++) {
            float4 qv = *(const float4*)&Qs[kk * 68 + tq * 4];
            float4 w  = *(const float4*)&Ws[kk * 32 + ti * 4];
            float4 s2 = *(const float4*)&Ss[kk * 32 + ti * 4];
            float qs[4] = {qv.x, qv.y, qv.z, qv.w};
            #pragma unroll
            for (int qq = 0; qq < 4; qq++) {
                float t;
                t = fmaf(w.x, qs[qq], -s2.x); acc[qq][0] = fmaf(qs[qq], t, acc[qq][0]);
                t = fmaf(w.y, qs[qq], -s2.y); acc[qq][1] = fmaf(qs[qq], t, acc[qq][1]);
                t = fmaf(w.z, qs[qq], -s2.z); acc[qq][2] = fmaf(qs[qq], t, acc[qq][2]);
                t = fmaf(w.w, qs[qq], -s2.w); acc[qq][3] = fmaf(qs[qq], t, acc[qq][3]);
            }
        }
    }

    float* P = g_P[ks];
    #pragma unroll
    for (int qq = 0; qq < 4; qq++) {
        int j = jb + tq * 4 + qq;
        *(float4*)&P[j * WAY + ti * 4] =
            make_float4(acc[qq][0], acc[qq][1], acc[qq][2], acc[qq][3]);
    }
}

// ---------------------------------------------------------------------------
// Kernel 5: out[j,i] = -sqrt(max(A[i] + sum_ks P[ks][j,i], 0)),
//           A[i] = sum_chunk Apart[chunk][i].  grid 128, block 256.
// ---------------------------------------------------------------------------
__global__ void finalize_kernel(float* __restrict__ out) {
    int gid = blockIdx.x * 256 + threadIdx.x;
    int base = gid * 4;
    float4 s = *(const float4*)&g_P[0][base];
    #pragma unroll
    for (int ks = 1; ks < KSPLIT; ks++) {
        float4 p = *(const float4*)&g_P[ks][base];
        s.x += p.x; s.y += p.y; s.z += p.z; s.w += p.w;
    }
    int i = base & 31;
    float4 a = *(const float4*)&g_Apart[0][i];
    #pragma unroll
    for (int c = 1; c < NCHUNK; c++) {
        float4 p = *(const float4*)&g_Apart[c][i];
        a.x += p.x; a.y += p.y; a.z += p.z; a.w += p.w;
    }
    float4 o;
    o.x = -sqrtf(fmaxf(a.x + s.x, 0.f));
    o.y = -sqrtf(fmaxf(a.y + s.y, 0.f));
    o.z = -sqrtf(fmaxf(a.z + s.z, 0.f));
    o.w = -sqrtf(fmaxf(a.w + s.w, 0.f));
    *(float4*)&out[base] = o;
}

// ---------------------------------------------------------------------------
extern "C" void kernel_launch(void* const* d_in, const int* in_sizes, int n_in,
                              void* d_out, int out_size) {
    const float* S  = (const float*)d_in[0];  // [32, 640]
    const float* Q  = (const float*)d_in[1];  // [32, 128, 640]
    const float* W1 = (const float*)d_in[2];  // [640, 1280]
    const float* b1 = (const float*)d_in[3];  // [640]
    const float* W2 = (const float*)d_in[4];  // [640, 640]
    const float* b2 = (const float*)d_in[5];  // [640]
    float* out = (float*)d_out;               // [4096, 32]

    uv_kernel<<<160, 256>>>(S, W1);
    gemm2_partial<<<dim3(MPAD / 64, FEAT / 64, KS2), 256>>>(W2, b1);
    ctx_prep_kernel<<<dim3(NCHUNK, WAY), 128>>>(S, b2);
    dist_partial<<<dim3(NQ / 64, KSPLIT), 128>>>(Q);
    finalize_kernel<<<NQ * WAY / (256 * 4), 256>>>(out);
}

// round 8
// speedup vs baseline: 1.4951x; 1.1246x over previous
#include <cuda_runtime.h>
#include <math.h>

#define WAY  32
#define QRY  128
#define FEAT 640
#define NQ   (WAY*QRY)      // 4096
#define NPAIR (WAY*(WAY-1)) // 992
#define MPAD 1024           // padded M for gemm2

#define KSPLIT 16           // dist k-split
#define KSEG   (FEAT/KSPLIT)   // 40

#define KS2    10           // gemm2 k-split
#define KSEG2  (FEAT/KS2)   // 64  (exactly 2 subtiles of 32)

#define NCHUNK 5            // ctx_prep n-chunks of 128

// Scratch (device globals; no allocation allowed)
__device__ __align__(16) float g_U[WAY*FEAT];
__device__ __align__(16) float g_V[WAY*FEAT];
__device__ __align__(16) float g_Wt[FEAT*WAY];    // w[f][i] = context1^4, f-major
__device__ __align__(16) float g_WS2t[FEAT*WAY];  // 2*w*s,  f-major
__device__ __align__(16) float g_Apart[NCHUNK][WAY]; // partials of sum_f w*s^2
__device__ __align__(16) float g_P[KSPLIT][NQ*WAY];     // distance partials (8 MB)
__device__ __align__(16) float g_P2[KS2][NPAIR*FEAT];   // gemm2 partials (25.4 MB)

__device__ __forceinline__ float leaky(float x) { return x > 0.f ? x : 0.2f * x; }

// ---------------------------------------------------------------------------
// Kernel 1: U = S @ W1[:, :640]^T, V = S @ W1[:, 640:]^T   (both [32,640])
// grid 160, block 256. Each warp: one output column c, 32 classes (one/lane).
// ---------------------------------------------------------------------------
__global__ void uv_kernel(const float* __restrict__ S, const float* __restrict__ W1) {
    __shared__ float St[320 * 33];
    int tid = threadIdx.x;
    int c = blockIdx.x * 8 + (tid >> 5);   // combined output column 0..1279
    int i = tid & 31;                      // class
    int half = (c >= FEAT) ? 1 : 0;
    int o = c - half * FEAT;
    const float* w1row = W1 + o * (2 * FEAT) + half * FEAT;

    float a0 = 0.f, a1 = 0.f, a2 = 0.f, a3 = 0.f;
    for (int k0 = 0; k0 < FEAT; k0 += 320) {
        __syncthreads();
        #pragma unroll
        for (int r = 0; r < 10; r++) {
            int idx4 = r * 256 + tid;          // 2560 float4
            int ii = idx4 / 80;
            int kk4 = (idx4 - ii * 80) * 4;
            float4 v = *(const float4*)&S[ii * FEAT + k0 + kk4];
            St[(kk4 + 0) * 33 + ii] = v.x;
            St[(kk4 + 1) * 33 + ii] = v.y;
            St[(kk4 + 2) * 33 + ii] = v.z;
            St[(kk4 + 3) * 33 + ii] = v.w;
        }
        __syncthreads();
        #pragma unroll 4
        for (int kk = 0; kk < 320; kk += 4) {
            float4 wv = *(const float4*)&w1row[k0 + kk];
            a0 = fmaf(St[(kk + 0) * 33 + i], wv.x, a0);
            a1 = fmaf(St[(kk + 1) * 33 + i], wv.y, a1);
            a2 = fmaf(St[(kk + 2) * 33 + i], wv.z, a2);
            a3 = fmaf(St[(kk + 3) * 33 + i], wv.w, a3);
        }
    }
    float acc = (a0 + a1) + (a2 + a3);
    if (half) g_V[i * FEAT + o] = acc;
    else      g_U[i * FEAT + o] = acc;
}

// ---------------------------------------------------------------------------
// Kernel 2: flat GEMM partials. X1[r,k] = leaky(U[i,k]+V[j,k]+b1[k]),
//   r = i*31+p, j = p<i?p:p+1.  P2[ks][r][n] = sum_{k in seg} X1[r,k]*W2[n,k]
// grid (8 m-tiles, 10 n-tiles, KS2=10), block 128. Tile 128m x 64n,
// k-subtile 32 (KSEG2=64 -> exactly 2). Thread tile 8m x 8n (split halves)
// -> 1 B LDS per FMA, conflict-free LDS.128 reads.
// ---------------------------------------------------------------------------
__global__ void __launch_bounds__(128) gemm2_partial(const float* __restrict__ W2,
                                                     const float* __restrict__ b1) {
    __shared__ float Xs[32 * 132];  // [kk][m], 128m + pad
    __shared__ float Ws[32 * 68];   // [kk][n], 64n + pad

    int m0 = blockIdx.x * 128;
    int n0 = blockIdx.y * 64;
    int ks = blockIdx.z;
    int kbase = ks * KSEG2;
    int tid = threadIdx.x;
    int tm = tid >> 3;    // 0..15 -> m in {tm*4..+3} u {64+tm*4..+3}
    int tn = tid & 7;     // 0..7  -> n in {tn*4..+3} u {32+tn*4..+3}

    float acc[8][8];
    #pragma unroll
    for (int a = 0; a < 8; a++)
        #pragma unroll
        for (int b = 0; b < 8; b++) acc[a][b] = 0.f;

    #pragma unroll
    for (int kt = 0; kt < KSEG2; kt += 32) {
        int k0 = kbase + kt;
        __syncthreads();
        // Stage X1 tile (128m x 32k): 1024 float4, 8 per thread.
        #pragma unroll
        for (int rr = 0; rr < 8; rr++) {
            int idx4 = rr * 128 + tid;
            int rl  = idx4 >> 3;           // 0..127
            int kk4 = (idx4 & 7) * 4;      // 0..28
            int r = m0 + rl;
            float4 v;
            if (r < NPAIR) {
                int i = r / 31;
                int p = r - i * 31;
                int j = (p < i) ? p : p + 1;
                float4 u4 = *(const float4*)&g_U[i * FEAT + k0 + kk4];
                float4 v4 = *(const float4*)&g_V[j * FEAT + k0 + kk4];
                float4 b4 = *(const float4*)&b1[k0 + kk4];
                v.x = leaky(u4.x + v4.x + b4.x);
                v.y = leaky(u4.y + v4.y + b4.y);
                v.z = leaky(u4.z + v4.z + b4.z);
                v.w = leaky(u4.w + v4.w + b4.w);
            } else v = make_float4(0.f, 0.f, 0.f, 0.f);
            Xs[(kk4 + 0) * 132 + rl] = v.x;
            Xs[(kk4 + 1) * 132 + rl] = v.y;
            Xs[(kk4 + 2) * 132 + rl] = v.z;
            Xs[(kk4 + 3) * 132 + rl] = v.w;
        }
        // Stage W2 tile (64n x 32k) transposed: 512 float4, 4 per thread.
        #pragma unroll
        for (int rr = 0; rr < 4; rr++) {
            int idx4 = rr * 128 + tid;
            int nl  = idx4 >> 3;           // 0..63
            int kk4 = (idx4 & 7) * 4;
            float4 v = *(const float4*)&W2[(n0 + nl) * FEAT + k0 + kk4];
            Ws[(kk4 + 0) * 68 + nl] = v.x;
            Ws[(kk4 + 1) * 68 + nl] = v.y;
            Ws[(kk4 + 2) * 68 + nl] = v.z;
            Ws[(kk4 + 3) * 68 + nl] = v.w;
        }
        __syncthreads();
        #pragma unroll 4
        for (int kk = 0; kk < 32; kk++) {
            float4 x0 = *(const float4*)&Xs[kk * 132 + tm * 4];
            float4 x1 = *(const float4*)&Xs[kk * 132 + 64 + tm * 4];
            float4 w0 = *(const float4*)&Ws[kk * 68 + tn * 4];
            float4 w1 = *(const float4*)&Ws[kk * 68 + 32 + tn * 4];
            float xs[8] = {x0.x, x0.y, x0.z, x0.w, x1.x, x1.y, x1.z, x1.w};
            float ws[8] = {w0.x, w0.y, w0.z, w0.w, w1.x, w1.y, w1.z, w1.w};
            #pragma unroll
            for (int mm = 0; mm < 8; mm++)
                #pragma unroll
                for (int nn = 0; nn < 8; nn++)
                    acc[mm][nn] = fmaf(xs[mm], ws[nn], acc[mm][nn]);
        }
    }

    float* P = g_P2[ks];
    #pragma unroll
    for (int mh = 0; mh < 2; mh++)
        #pragma unroll
        for (int mm = 0; mm < 4; mm++) {
            int r = m0 + mh * 64 + tm * 4 + mm;
            if (r < NPAIR) {
                *(float4*)&P[r * FEAT + n0 + tn * 4] =
                    make_float4(acc[mh*4+mm][0], acc[mh*4+mm][1],
                                acc[mh*4+mm][2], acc[mh*4+mm][3]);
                *(float4*)&P[r * FEAT + n0 + 32 + tn * 4] =
                    make_float4(acc[mh*4+mm][4], acc[mh*4+mm][5],
                                acc[mh*4+mm][6], acc[mh*4+mm][7]);
            }
        }
}

// ---------------------------------------------------------------------------
// Kernel 3 (fused reduce+prep): for class i, n = chunk*128 + tid:
//   ctx = (1/31) * sum_{p<31} leaky(sum_ks P2[ks][i*31+p][n] + b2[n])
//   w = ctx^4; Wt[n][i] = w; WS2t[n][i] = 2*w*s; Apart[chunk][i] = sum_n w*s^2
// grid (5 chunks, 32 classes), block 128.
// ---------------------------------------------------------------------------
__global__ void __launch_bounds__(128) ctx_prep_kernel(const float* __restrict__ S,
                                                       const float* __restrict__ b2) {
    __shared__ float rs[128];
    int i = blockIdx.y;
    int n = blockIdx.x * 128 + threadIdx.x;
    int tid = threadIdx.x;

    float bb = b2[n];
    float ssum = 0.f;
    int rbase = i * 31;
    #pragma unroll 4
    for (int p = 0; p < 31; p++) {
        int off = (rbase + p) * FEAT + n;
        float v = 0.f;
        #pragma unroll
        for (int ks = 0; ks < KS2; ks++) v += g_P2[ks][off];
        ssum += leaky(v + bb);
    }
    float ctx = ssum * (1.0f / 31.0f);
    float c2 = ctx * ctx;
    float w = c2 * c2;
    float s = S[i * FEAT + n];
    g_Wt[n * WAY + i] = w;
    g_WS2t[n * WAY + i] = 2.0f * w * s;

    rs[tid] = w * s * s;
    __syncthreads();
    for (int st = 64; st > 0; st >>= 1) {
        if (tid < st) rs[tid] += rs[tid + st];
        __syncthreads();
    }
    if (tid == 0) g_Apart[blockIdx.x][i] = rs[0];
}

// ---------------------------------------------------------------------------
// Kernel 4: dist partials. grid (64 q-tiles, KSPLIT=16), block 128.
// Block tile 64q x 32i x 40k, staged once (single sync). Thread tile 4q x 4i.
// ---------------------------------------------------------------------------
__global__ void __launch_bounds__(128) dist_partial(const float* __restrict__ Q) {
    __shared__ float Qs[40 * 68];   // [kk][q]
    __shared__ float Ws[40 * 32];   // [kk][i]
    __shared__ float Ss[40 * 32];   // [kk][i]

    int jb = blockIdx.x * 64;
    int ks = blockIdx.y;
    int k0 = ks * KSEG;
    int tid = threadIdx.x;
    int tq = tid >> 3;   // 0..15 -> q = tq*4
    int ti = tid & 7;    // 0..7  -> i = ti*4

    // Stage Q (64q x 40k): 640 float4, 5 per thread.
    #pragma unroll
    for (int r = 0; r < 5; r++) {
        int idx4 = r * 128 + tid;
        int q   = idx4 / 10;
        int kk4 = (idx4 - q * 10) * 4;
        float4 v = *(const float4*)&Q[(jb + q) * FEAT + k0 + kk4];
        Qs[(kk4 + 0) * 68 + q] = v.x;
        Qs[(kk4 + 1) * 68 + q] = v.y;
        Qs[(kk4 + 2) * 68 + q] = v.z;
        Qs[(kk4 + 3) * 68 + q] = v.w;
    }
    // Stage w / ws2 (40k x 32i, f-major flat): 320 float4 each.
    #pragma unroll
    for (int r = 0; r < 3; r++) {
        int idx4 = r * 128 + tid;
        if (idx4 < 320) {
            *(float4*)&Ws[idx4 * 4] = *(const float4*)&g_Wt[k0 * WAY + idx4 * 4];
            *(float4*)&Ss[idx4 * 4] = *(const float4*)&g_WS2t[k0 * WAY + idx4 * 4];
        }
    }
    __syncthreads();

    float acc[4][4];
    #pragma unroll
    for (int a = 0; a < 4; a++)
        #pragma unroll
        for (int b = 0; b < 4; b++) acc[a][b] = 0.f;

    #pragma unroll 4
    for (int kk = 0; kk < KSEG; kk++) {
        float4 qv = *(const float4*)&Qs[kk * 68 + tq * 4];
        float4 w  = *(const float4*)&Ws[kk * 32 + ti * 4];
        float4 s2 = *(const float4*)&Ss[kk * 32 + ti * 4];
        float qs[4] = {qv.x, qv.y, qv.z, qv.w};
        #pragma unroll
        for (int qq = 0; qq < 4; qq++) {
            float t;
            t = fmaf(w.x, qs[qq], -s2.x); acc[qq][0] = fmaf(qs[qq], t, acc[qq][0]);
            t = fmaf(w.y, qs[qq], -s2.y); acc[qq][1] = fmaf(qs[qq], t, acc[qq][1]);
            t = fmaf(w.z, qs[qq], -s2.z); acc[qq][2] = fmaf(qs[qq], t, acc[qq][2]);
            t = fmaf(w.w, qs[qq], -s2.w); acc[qq][3] = fmaf(qs[qq], t, acc[qq][3]);
        }
    }

    float* P = g_P[ks];
    #pragma unroll
    for (int qq = 0; qq < 4; qq++) {
        int j = jb + tq * 4 + qq;
        *(float4*)&P[j * WAY + ti * 4] =
            make_float4(acc[qq][0], acc[qq][1], acc[qq][2], acc[qq][3]);
    }
}

// ---------------------------------------------------------------------------
// Kernel 5: out[j,i] = -sqrt(max(A[i] + sum_ks P[ks][j,i], 0)),
//           A[i] = sum_chunk Apart[chunk][i].  grid 128, block 256.
// ---------------------------------------------------------------------------
__global__ void finalize_kernel(float* __restrict__ out) {
    int gid = blockIdx.x * 256 + threadIdx.x;
    int base = gid * 4;
    float4 s = *(const float4*)&g_P[0][base];
    #pragma unroll
    for (int ks = 1; ks < KSPLIT; ks++) {
        float4 p = *(const float4*)&g_P[ks][base];
        s.x += p.x; s.y += p.y; s.z += p.z; s.w += p.w;
    }
    int i = base & 31;
    float4 a = *(const float4*)&g_Apart[0][i];
    #pragma unroll
    for (int c = 1; c < NCHUNK; c++) {
        float4 p = *(const float4*)&g_Apart[c][i];
        a.x += p.x; a.y += p.y; a.z += p.z; a.w += p.w;
    }
    float4 o;
    o.x = -sqrtf(fmaxf(a.x + s.x, 0.f));
    o.y = -sqrtf(fmaxf(a.y + s.y, 0.f));
    o.z = -sqrtf(fmaxf(a.z + s.z, 0.f));
    o.w = -sqrtf(fmaxf(a.w + s.w, 0.f));
    *(float4*)&out[base] = o;
}

// ---------------------------------------------------------------------------
extern "C" void kernel_launch(void* const* d_in, const int* in_sizes, int n_in,
                              void* d_out, int out_size) {
    const float* S  = (const float*)d_in[0];  // [32, 640]
    const float* Q  = (const float*)d_in[1];  // [32, 128, 640]
    const float* W1 = (const float*)d_in[2];  // [640, 1280]
    const float* b1 = (const float*)d_in[3];  // [640]
    const float* W2 = (const float*)d_in[4];  // [640, 640]
    const float* b2 = (const float*)d_in[5];  // [640]
    float* out = (float*)d_out;               // [4096, 32]

    uv_kernel<<<160, 256>>>(S, W1);
    gemm2_partial<<<dim3(MPAD / 128, FEAT / 64, KS2), 128>>>(W2, b1);
    ctx_prep_kernel<<<dim3(NCHUNK, WAY), 128>>>(S, b2);
    dist_partial<<<dim3(NQ / 64, KSPLIT), 128>>>(Q);
    finalize_kernel<<<NQ * WAY / (256 * 4), 256>>>(out);
}

// round 10
// speedup vs baseline: 1.5334x; 1.0256x over previous
#include <cuda_runtime.h>
#include <cuda_bf16.h>
#include <math.h>
#include <stdint.h>

#define WAY  32
#define QRY  128
#define FEAT 640
#define NQ   (WAY*QRY)      // 4096
#define NPAIR (WAY*(WAY-1)) // 992
#define MPAD 1024

#define KSPLIT 16           // dist k-split
#define KSEG   (FEAT/KSPLIT)   // 40
#define NCHUNK 5            // ctx_prep n-chunks of 128

// Scratch (device globals; no allocation allowed)
__device__ __align__(16) float g_U[WAY*FEAT];
__device__ __align__(16) float g_V[WAY*FEAT];
__device__ __align__(16) float g_X2[NPAIR*FEAT];  // gemm2 result (2.5 MB)
__device__ __align__(16) float g_Wt[FEAT*WAY];    // w[f][i] = context1^4, f-major
__device__ __align__(16) float g_WS2t[FEAT*WAY];  // 2*w*s,  f-major
__device__ __align__(16) float g_Apart[NCHUNK][WAY];
__device__ __align__(16) float g_P[KSPLIT][NQ*WAY];   // distance partials (8 MB)

__device__ __forceinline__ float leaky(float x) { return x > 0.f ? x : 0.2f * x; }

__device__ __forceinline__ uint32_t smem_u32(const void* p) {
    uint32_t a;
    asm("{ .reg .u64 t; cvta.to.shared.u64 t, %1; cvt.u32.u64 %0, t; }" : "=r"(a) : "l"(p));
    return a;
}

__device__ __forceinline__ void ldm_x4(uint32_t* r, uint32_t addr) {
    asm volatile("ldmatrix.sync.aligned.m8n8.x4.shared.b16 {%0,%1,%2,%3}, [%4];"
                 : "=r"(r[0]), "=r"(r[1]), "=r"(r[2]), "=r"(r[3]) : "r"(addr));
}
__device__ __forceinline__ void ldm_x2(uint32_t* r, uint32_t addr) {
    asm volatile("ldmatrix.sync.aligned.m8n8.x2.shared.b16 {%0,%1}, [%2];"
                 : "=r"(r[0]), "=r"(r[1]) : "r"(addr));
}
__device__ __forceinline__ void mma_bf16(float* c, const uint32_t* a, const uint32_t* b) {
    asm volatile(
        "mma.sync.aligned.m16n8k16.row.col.f32.bf16.bf16.f32 "
        "{%0,%1,%2,%3}, {%4,%5,%6,%7}, {%8,%9}, {%0,%1,%2,%3};"
        : "+f"(c[0]), "+f"(c[1]), "+f"(c[2]), "+f"(c[3])
        : "r"(a[0]), "r"(a[1]), "r"(a[2]), "r"(a[3]), "r"(b[0]), "r"(b[1]));
}

__device__ __forceinline__ void split4(float4 v, uint2& hi, uint2& lo) {
    __nv_bfloat16 hx = __float2bfloat16(v.x), hy = __float2bfloat16(v.y),
                  hz = __float2bfloat16(v.z), hw = __float2bfloat16(v.w);
    float rx = v.x - __bfloat162float(hx), ry = v.y - __bfloat162float(hy),
          rz = v.z - __bfloat162float(hz), rw = v.w - __bfloat162float(hw);
    __nv_bfloat16 lx = __float2bfloat16(rx), ly = __float2bfloat16(ry),
                  lz = __float2bfloat16(rz), lw = __float2bfloat16(rw);
    hi.x = (uint32_t)__bfloat16_as_ushort(hx) | ((uint32_t)__bfloat16_as_ushort(hy) << 16);
    hi.y = (uint32_t)__bfloat16_as_ushort(hz) | ((uint32_t)__bfloat16_as_ushort(hw) << 16);
    lo.x = (uint32_t)__bfloat16_as_ushort(lx) | ((uint32_t)__bfloat16_as_ushort(ly) << 16);
    lo.y = (uint32_t)__bfloat16_as_ushort(lz) | ((uint32_t)__bfloat16_as_ushort(lw) << 16);
}

// ---------------------------------------------------------------------------
// Kernel 1: U = S @ W1[:, :640]^T, V = S @ W1[:, 640:]^T   (both [32,640])
// ---------------------------------------------------------------------------
__global__ void uv_kernel(const float* __restrict__ S, const float* __restrict__ W1) {
    __shared__ float St[320 * 33];
    int tid = threadIdx.x;
    int c = blockIdx.x * 8 + (tid >> 5);
    int i = tid & 31;
    int half = (c >= FEAT) ? 1 : 0;
    int o = c - half * FEAT;
    const float* w1row = W1 + o * (2 * FEAT) + half * FEAT;

    float a0 = 0.f, a1 = 0.f, a2 = 0.f, a3 = 0.f;
    for (int k0 = 0; k0 < FEAT; k0 += 320) {
        __syncthreads();
        #pragma unroll
        for (int r = 0; r < 10; r++) {
            int idx4 = r * 256 + tid;
            int ii = idx4 / 80;
            int kk4 = (idx4 - ii * 80) * 4;
            float4 v = *(const float4*)&S[ii * FEAT + k0 + kk4];
            St[(kk4 + 0) * 33 + ii] = v.x;
            St[(kk4 + 1) * 33 + ii] = v.y;
            St[(kk4 + 2) * 33 + ii] = v.z;
            St[(kk4 + 3) * 33 + ii] = v.w;
        }
        __syncthreads();
        #pragma unroll 4
        for (int kk = 0; kk < 320; kk += 4) {
            float4 wv = *(const float4*)&w1row[k0 + kk];
            a0 = fmaf(St[(kk + 0) * 33 + i], wv.x, a0);
            a1 = fmaf(St[(kk + 1) * 33 + i], wv.y, a1);
            a2 = fmaf(St[(kk + 2) * 33 + i], wv.z, a2);
            a3 = fmaf(St[(kk + 3) * 33 + i], wv.w, a3);
        }
    }
    float acc = (a0 + a1) + (a2 + a3);
    if (half) g_V[i * FEAT + o] = acc;
    else      g_U[i * FEAT + o] = acc;
}

// ---------------------------------------------------------------------------
// Kernel 2 (tensor cores via mma.sync): X2 = X1 @ W2^T, bf16 hi/lo split,
// fp32 accum. grid (16 m-tiles, 10 n-tiles), block 128 (4 warps).
// Block tile 64m x 64n; warp tile 64m x 16n; K chunks of 64 in smem.
// Smem rows stride 72 bf16 (144 B) -> conflict-free ldmatrix.
// ---------------------------------------------------------------------------
__global__ void __launch_bounds__(128) gemm2_mma(const float* __restrict__ W2,
                                                 const float* __restrict__ b1) {
    __shared__ __align__(16) __nv_bfloat16 Xhi[64 * 72], Xlo[64 * 72];
    __shared__ __align__(16) __nv_bfloat16 Whi[64 * 72], Wlo[64 * 72];

    int tid = threadIdx.x;
    int wid = tid >> 5, lane = tid & 31;
    int m0 = blockIdx.x * 64, n0 = blockIdx.y * 64;
    int nw = wid * 16;   // warp's n-offset within tile

    uint32_t xhi_b = smem_u32(Xhi), xlo_b = smem_u32(Xlo);
    uint32_t whi_b = smem_u32(Whi), wlo_b = smem_u32(Wlo);

    float acc[4][2][4];
    #pragma unroll
    for (int a = 0; a < 4; a++)
        #pragma unroll
        for (int b = 0; b < 2; b++)
            #pragma unroll
            for (int cc = 0; cc < 4; cc++) acc[a][b][cc] = 0.f;

    // ldmatrix source addresses (element offsets; stride 72 bf16 per row)
    int arow = lane & 15, acolsel = (lane >> 4) * 8;    // A: x4
    int brow = lane & 7,  bcolsel = ((lane >> 3) & 1) * 8; // B: x2 (lanes 0-15)

    for (int c = 0; c < 10; c++) {
        int k0 = c * 64;
        __syncthreads();
        // Stage X1 (64m x 64k) hi/lo: 1024 float4, 8 per thread.
        #pragma unroll
        for (int r = 0; r < 8; r++) {
            int idx4 = r * 128 + tid;
            int rl  = idx4 >> 4;
            int k4  = (idx4 & 15) * 4;
            int row = m0 + rl;
            float4 v;
            if (row < NPAIR) {
                int i = row / 31;
                int p = row - i * 31;
                int j = (p < i) ? p : p + 1;
                float4 u4 = *(const float4*)&g_U[i * FEAT + k0 + k4];
                float4 v4 = *(const float4*)&g_V[j * FEAT + k0 + k4];
                float4 b4 = *(const float4*)&b1[k0 + k4];
                v.x = leaky(u4.x + v4.x + b4.x);
                v.y = leaky(u4.y + v4.y + b4.y);
                v.z = leaky(u4.z + v4.z + b4.z);
                v.w = leaky(u4.w + v4.w + b4.w);
            } else v = make_float4(0.f, 0.f, 0.f, 0.f);
            uint2 hi, lo; split4(v, hi, lo);
            *(uint2*)&Xhi[rl * 72 + k4] = hi;
            *(uint2*)&Xlo[rl * 72 + k4] = lo;
        }
        // Stage W2 (64n x 64k) hi/lo.
        #pragma unroll
        for (int r = 0; r < 8; r++) {
            int idx4 = r * 128 + tid;
            int nl = idx4 >> 4;
            int k4 = (idx4 & 15) * 4;
            float4 v = *(const float4*)&W2[(n0 + nl) * FEAT + k0 + k4];
            uint2 hi, lo; split4(v, hi, lo);
            *(uint2*)&Whi[nl * 72 + k4] = hi;
            *(uint2*)&Wlo[nl * 72 + k4] = lo;
        }
        __syncthreads();

        #pragma unroll
        for (int kk = 0; kk < 64; kk += 16) {
            uint32_t ah[4][4], al[4][4], bh[2][2], bl[2][2];
            #pragma unroll
            for (int mt = 0; mt < 4; mt++) {
                uint32_t off = ((mt * 16 + arow) * 72 + kk + acolsel) * 2;
                ldm_x4(ah[mt], xhi_b + off);
                ldm_x4(al[mt], xlo_b + off);
            }
            #pragma unroll
            for (int nt = 0; nt < 2; nt++) {
                uint32_t off = ((nw + nt * 8 + brow) * 72 + kk + bcolsel) * 2;
                ldm_x2(bh[nt], whi_b + off);
                ldm_x2(bl[nt], wlo_b + off);
            }
            #pragma unroll
            for (int mt = 0; mt < 4; mt++)
                #pragma unroll
                for (int nt = 0; nt < 2; nt++) {
                    mma_bf16(acc[mt][nt], ah[mt], bh[nt]);
                    mma_bf16(acc[mt][nt], al[mt], bh[nt]);
                    mma_bf16(acc[mt][nt], ah[mt], bl[nt]);
                }
        }
    }

    // Epilogue: c-frag mapping (m16n8): row = group + 8*(reg>=2), col = 2*tig + (reg&1)
    int group = lane >> 2, tig = lane & 3;
    #pragma unroll
    for (int mt = 0; mt < 4; mt++)
        #pragma unroll
        for (int nt = 0; nt < 2; nt++) {
            int colb = n0 + nw + nt * 8 + tig * 2;
            int r0 = m0 + mt * 16 + group;
            int r1 = r0 + 8;
            if (r0 < NPAIR)
                *(float2*)&g_X2[r0 * FEAT + colb] = make_float2(acc[mt][nt][0], acc[mt][nt][1]);
            if (r1 < NPAIR)
                *(float2*)&g_X2[r1 * FEAT + colb] = make_float2(acc[mt][nt][2], acc[mt][nt][3]);
        }
}

// ---------------------------------------------------------------------------
// Kernel 3: ctx = (1/31) sum_p leaky(X2 + b2); w = ctx^4; emit Wt/WS2t/Apart.
// grid (5 chunks, 32 classes), block 128.
// ---------------------------------------------------------------------------
__global__ void __launch_bounds__(128) ctx_prep_kernel(const float* __restrict__ S,
                                                       const float* __restrict__ b2) {
    __shared__ float rs[128];
    int i = blockIdx.y;
    int n = blockIdx.x * 128 + threadIdx.x;
    int tid = threadIdx.x;

    float bb = b2[n];
    float ssum = 0.f;
    int rbase = i * 31;
    #pragma unroll 4
    for (int p = 0; p < 31; p++)
        ssum += leaky(g_X2[(rbase + p) * FEAT + n] + bb);
    float ctx = ssum * (1.0f / 31.0f);
    float c2 = ctx * ctx;
    float w = c2 * c2;
    float s = S[i * FEAT + n];
    g_Wt[n * WAY + i] = w;
    g_WS2t[n * WAY + i] = 2.0f * w * s;

    rs[tid] = w * s * s;
    __syncthreads();
    for (int st = 64; st > 0; st >>= 1) {
        if (tid < st) rs[tid] += rs[tid + st];
        __syncthreads();
    }
    if (tid == 0) g_Apart[blockIdx.x][i] = rs[0];
}

// ---------------------------------------------------------------------------
// Kernel 4: dist partials. grid (64 q-tiles, KSPLIT=16), block 128.
// ---------------------------------------------------------------------------
__global__ void __launch_bounds__(128) dist_partial(const float* __restrict__ Q) {
    __shared__ float Qs[40 * 68];
    __shared__ float Ws[40 * 32];
    __shared__ float Ss[40 * 32];

    int jb = blockIdx.x * 64;
    int ks = blockIdx.y;
    int k0 = ks * KSEG;
    int tid = threadIdx.x;
    int tq = tid >> 3;
    int ti = tid & 7;

    #pragma unroll
    for (int r = 0; r < 5; r++) {
        int idx4 = r * 128 + tid;
        int q   = idx4 / 10;
        int kk4 = (idx4 - q * 10) * 4;
        float4 v = *(const float4*)&Q[(jb + q) * FEAT + k0 + kk4];
        Qs[(kk4 + 0) * 68 + q] = v.x;
        Qs[(kk4 + 1) * 68 + q] = v.y;
        Qs[(kk4 + 2) * 68 + q] = v.z;
        Qs[(kk4 + 3) * 68 + q] = v.w;
    }
    #pragma unroll
    for (int r = 0; r < 3; r++) {
        int idx4 = r * 128 + tid;
        if (idx4 < 320) {
            *(float4*)&Ws[idx4 * 4] = *(const float4*)&g_Wt[k0 * WAY + idx4 * 4];
            *(float4*)&Ss[idx4 * 4] = *(const float4*)&g_WS2t[k0 * WAY + idx4 * 4];
        }
    }
    __syncthreads();

    float acc[4][4];
    #pragma unroll
    for (int a = 0; a < 4; a++)
        #pragma unroll
        for (int b = 0; b < 4; b++) acc[a][b] = 0.f;

    #pragma unroll 4
    for (int kk = 0; kk < KSEG; kk++) {
        float4 qv = *(const float4*)&Qs[kk * 68 + tq * 4];
        float4 w  = *(const float4*)&Ws[kk * 32 + ti * 4];
        float4 s2 = *(const float4*)&Ss[kk * 32 + ti * 4];
        float qs[4] = {qv.x, qv.y, qv.z, qv.w};
        #pragma unroll
        for (int qq = 0; qq < 4; qq++) {
            float t;
            t = fmaf(w.x, qs[qq], -s2.x); acc[qq][0] = fmaf(qs[qq], t, acc[qq][0]);
            t = fmaf(w.y, qs[qq], -s2.y); acc[qq][1] = fmaf(qs[qq], t, acc[qq][1]);
            t = fmaf(w.z, qs[qq], -s2.z); acc[qq][2] = fmaf(qs[qq], t, acc[qq][2]);
            t = fmaf(w.w, qs[qq], -s2.w); acc[qq][3] = fmaf(qs[qq], t, acc[qq][3]);
        }
    }

    float* P = g_P[ks];
    #pragma unroll
    for (int qq = 0; qq < 4; qq++) {
        int j = jb + tq * 4 + qq;
        *(float4*)&P[j * WAY + ti * 4] =
            make_float4(acc[qq][0], acc[qq][1], acc[qq][2], acc[qq][3]);
    }
}

// ---------------------------------------------------------------------------
// Kernel 5: out[j,i] = -sqrt(max(A[i] + sum_ks P[ks][j,i], 0))
// ---------------------------------------------------------------------------
__global__ void finalize_kernel(float* __restrict__ out) {
    int gid = blockIdx.x * 256 + threadIdx.x;
    int base = gid * 4;
    float4 s = *(const float4*)&g_P[0][base];
    #pragma unroll
    for (int ks = 1; ks < KSPLIT; ks++) {
        float4 p = *(const float4*)&g_P[ks][base];
        s.x += p.x; s.y += p.y; s.z += p.z; s.w += p.w;
    }
    int i = base & 31;
    float4 a = *(const float4*)&g_Apart[0][i];
    #pragma unroll
    for (int c = 1; c < NCHUNK; c++) {
        float4 p = *(const float4*)&g_Apart[c][i];
        a.x += p.x; a.y += p.y; a.z += p.z; a.w += p.w;
    }
    float4 o;
    o.x = -sqrtf(fmaxf(a.x + s.x, 0.f));
    o.y = -sqrtf(fmaxf(a.y + s.y, 0.f));
    o.z = -sqrtf(fmaxf(a.z + s.z, 0.f));
    o.w = -sqrtf(fmaxf(a.w + s.w, 0.f));
    *(float4*)&out[base] = o;
}

// ---------------------------------------------------------------------------
extern "C" void kernel_launch(void* const* d_in, const int* in_sizes, int n_in,
                              void* d_out, int out_size) {
    const float* S  = (const float*)d_in[0];
    const float* Q  = (const float*)d_in[1];
    const float* W1 = (const float*)d_in[2];
    const float* b1 = (const float*)d_in[3];
    const float* W2 = (const float*)d_in[4];
    const float* b2 = (const float*)d_in[5];
    float* out = (float*)d_out;

    uv_kernel<<<160, 256>>>(S, W1);
    gemm2_mma<<<dim3(MPAD / 64, FEAT / 64), 128>>>(W2, b1);
    ctx_prep_kernel<<<dim3(NCHUNK, WAY), 128>>>(S, b2);
    dist_partial<<<dim3(NQ / 64, KSPLIT), 128>>>(Q);
    finalize_kernel<<<NQ * WAY / (256 * 4), 256>>>(out);
}

// round 11
// speedup vs baseline: 1.6612x; 1.0833x over previous
#include <cuda_runtime.h>
#include <cuda_bf16.h>
#include <math.h>
#include <stdint.h>

#define WAY  32
#define QRY  128
#define FEAT 640
#define NQ   (WAY*QRY)      // 4096
#define NPAIR (WAY*(WAY-1)) // 992
#define MPAD 1024

#define DSPLIT 4            // dist k-split (over K'=1280)
#define DSEG   320          // K' per split
#define NCHUNK 5            // ctx_prep n-chunks of 128

// Scratch (device globals; no allocation allowed)
__device__ __align__(16) float g_U[WAY*FEAT];
__device__ __align__(16) float g_V[WAY*FEAT];
__device__ __align__(16) float g_X2[NPAIR*FEAT];            // gemm2 result
__device__ __align__(16) __nv_bfloat16 g_W2hi[FEAT*FEAT];   // W2 bf16 hi
__device__ __align__(16) __nv_bfloat16 g_W2lo[FEAT*FEAT];   // W2 bf16 lo
__device__ __align__(16) __nv_bfloat16 g_Bhi[WAY*2*FEAT];   // [w | -ws2] hi, [32][1280]
__device__ __align__(16) __nv_bfloat16 g_Blo[WAY*2*FEAT];   // [w | -ws2] lo
__device__ __align__(16) float g_Apart[NCHUNK][WAY];
__device__ __align__(16) float g_P[DSPLIT][NQ*WAY];         // distance partials

__device__ __forceinline__ float leaky(float x) { return x > 0.f ? x : 0.2f * x; }

__device__ __forceinline__ uint32_t smem_u32(const void* p) {
    uint32_t a;
    asm("{ .reg .u64 t; cvta.to.shared.u64 t, %1; cvt.u32.u64 %0, t; }" : "=r"(a) : "l"(p));
    return a;
}
__device__ __forceinline__ void ldm_x4(uint32_t* r, uint32_t addr) {
    asm volatile("ldmatrix.sync.aligned.m8n8.x4.shared.b16 {%0,%1,%2,%3}, [%4];"
                 : "=r"(r[0]), "=r"(r[1]), "=r"(r[2]), "=r"(r[3]) : "r"(addr));
}
__device__ __forceinline__ void ldm_x2(uint32_t* r, uint32_t addr) {
    asm volatile("ldmatrix.sync.aligned.m8n8.x2.shared.b16 {%0,%1}, [%2];"
                 : "=r"(r[0]), "=r"(r[1]) : "r"(addr));
}
__device__ __forceinline__ void mma_bf16(float* c, const uint32_t* a, const uint32_t* b) {
    asm volatile(
        "mma.sync.aligned.m16n8k16.row.col.f32.bf16.bf16.f32 "
        "{%0,%1,%2,%3}, {%4,%5,%6,%7}, {%8,%9}, {%0,%1,%2,%3};"
        : "+f"(c[0]), "+f"(c[1]), "+f"(c[2]), "+f"(c[3])
        : "r"(a[0]), "r"(a[1]), "r"(a[2]), "r"(a[3]), "r"(b[0]), "r"(b[1]));
}
__device__ __forceinline__ void split4(float4 v, uint2& hi, uint2& lo) {
    __nv_bfloat16 hx = __float2bfloat16(v.x), hy = __float2bfloat16(v.y),
                  hz = __float2bfloat16(v.z), hw = __float2bfloat16(v.w);
    float rx = v.x - __bfloat162float(hx), ry = v.y - __bfloat162float(hy),
          rz = v.z - __bfloat162float(hz), rw = v.w - __bfloat162float(hw);
    __nv_bfloat16 lx = __float2bfloat16(rx), ly = __float2bfloat16(ry),
                  lz = __float2bfloat16(rz), lw = __float2bfloat16(rw);
    hi.x = (uint32_t)__bfloat16_as_ushort(hx) | ((uint32_t)__bfloat16_as_ushort(hy) << 16);
    hi.y = (uint32_t)__bfloat16_as_ushort(hz) | ((uint32_t)__bfloat16_as_ushort(hw) << 16);
    lo.x = (uint32_t)__bfloat16_as_ushort(lx) | ((uint32_t)__bfloat16_as_ushort(ly) << 16);
    lo.y = (uint32_t)__bfloat16_as_ushort(lz) | ((uint32_t)__bfloat16_as_ushort(lw) << 16);
}
__device__ __forceinline__ void split1(float v, __nv_bfloat16& hi, __nv_bfloat16& lo) {
    hi = __float2bfloat16(v);
    lo = __float2bfloat16(v - __bfloat162float(hi));
}

// ---------------------------------------------------------------------------
// Kernel 1: U = S @ W1[:, :640]^T, V = S @ W1[:, 640:]^T; tail: split W2->bf16.
// ---------------------------------------------------------------------------
__global__ void uv_kernel(const float* __restrict__ S, const float* __restrict__ W1,
                          const float* __restrict__ W2) {
    __shared__ float St[320 * 33];
    int tid = threadIdx.x;
    int c = blockIdx.x * 8 + (tid >> 5);
    int i = tid & 31;
    int half = (c >= FEAT) ? 1 : 0;
    int o = c - half * FEAT;
    const float* w1row = W1 + o * (2 * FEAT) + half * FEAT;

    float a0 = 0.f, a1 = 0.f, a2 = 0.f, a3 = 0.f;
    for (int k0 = 0; k0 < FEAT; k0 += 320) {
        __syncthreads();
        #pragma unroll
        for (int r = 0; r < 10; r++) {
            int idx4 = r * 256 + tid;
            int ii = idx4 / 80;
            int kk4 = (idx4 - ii * 80) * 4;
            float4 v = *(const float4*)&S[ii * FEAT + k0 + kk4];
            St[(kk4 + 0) * 33 + ii] = v.x;
            St[(kk4 + 1) * 33 + ii] = v.y;
            St[(kk4 + 2) * 33 + ii] = v.z;
            St[(kk4 + 3) * 33 + ii] = v.w;
        }
        __syncthreads();
        #pragma unroll 4
        for (int kk = 0; kk < 320; kk += 4) {
            float4 wv = *(const float4*)&w1row[k0 + kk];
            a0 = fmaf(St[(kk + 0) * 33 + i], wv.x, a0);
            a1 = fmaf(St[(kk + 1) * 33 + i], wv.y, a1);
            a2 = fmaf(St[(kk + 2) * 33 + i], wv.z, a2);
            a3 = fmaf(St[(kk + 3) * 33 + i], wv.w, a3);
        }
    }
    float acc = (a0 + a1) + (a2 + a3);
    if (half) g_V[i * FEAT + o] = acc;
    else      g_U[i * FEAT + o] = acc;

    // Tail: W2 fp32 -> bf16 hi/lo (grid-stride, once per element).
    int nthr = gridDim.x * blockDim.x;
    for (int idx4 = blockIdx.x * blockDim.x + tid; idx4 < FEAT * FEAT / 4; idx4 += nthr) {
        float4 v = *(const float4*)&W2[idx4 * 4];
        uint2 hi, lo; split4(v, hi, lo);
        *(uint2*)&g_W2hi[idx4 * 4] = hi;
        *(uint2*)&g_W2lo[idx4 * 4] = lo;
    }
}

// ---------------------------------------------------------------------------
// Kernel 2 (mma.sync bf16 hi/lo): X2 = X1 @ W2^T, fp32 accum.
// grid (16 m-tiles, 10 n-tiles), block 128 (4 warps). Block 64m x 64n,
// warp 64m x 16n, K chunks of 64. Smem rows stride 72 bf16.
// ---------------------------------------------------------------------------
__global__ void __launch_bounds__(128) gemm2_mma(const float* __restrict__ b1) {
    __shared__ __align__(16) __nv_bfloat16 Xhi[64 * 72], Xlo[64 * 72];
    __shared__ __align__(16) __nv_bfloat16 Whi[64 * 72], Wlo[64 * 72];

    int tid = threadIdx.x;
    int wid = tid >> 5, lane = tid & 31;
    int m0 = blockIdx.x * 64, n0 = blockIdx.y * 64;
    int nw = wid * 16;

    uint32_t xhi_b = smem_u32(Xhi), xlo_b = smem_u32(Xlo);
    uint32_t whi_b = smem_u32(Whi), wlo_b = smem_u32(Wlo);

    float acc[4][2][4];
    #pragma unroll
    for (int a = 0; a < 4; a++)
        #pragma unroll
        for (int b = 0; b < 2; b++)
            #pragma unroll
            for (int cc = 0; cc < 4; cc++) acc[a][b][cc] = 0.f;

    int arow = lane & 15, acolsel = (lane >> 4) * 8;
    int brow = lane & 7,  bcolsel = ((lane >> 3) & 1) * 8;

    for (int c = 0; c < 10; c++) {
        int k0 = c * 64;
        __syncthreads();
        // Stage X1 (64m x 64k) hi/lo via leaky(U+V+b1), split on the fly.
        #pragma unroll
        for (int r = 0; r < 8; r++) {
            int idx4 = r * 128 + tid;
            int rl  = idx4 >> 4;
            int k4  = (idx4 & 15) * 4;
            int row = m0 + rl;
            float4 v;
            if (row < NPAIR) {
                int i = row / 31;
                int p = row - i * 31;
                int j = (p < i) ? p : p + 1;
                float4 u4 = *(const float4*)&g_U[i * FEAT + k0 + k4];
                float4 v4 = *(const float4*)&g_V[j * FEAT + k0 + k4];
                float4 b4 = *(const float4*)&b1[k0 + k4];
                v.x = leaky(u4.x + v4.x + b4.x);
                v.y = leaky(u4.y + v4.y + b4.y);
                v.z = leaky(u4.z + v4.z + b4.z);
                v.w = leaky(u4.w + v4.w + b4.w);
            } else v = make_float4(0.f, 0.f, 0.f, 0.f);
            uint2 hi, lo; split4(v, hi, lo);
            *(uint2*)&Xhi[rl * 72 + k4] = hi;
            *(uint2*)&Xlo[rl * 72 + k4] = lo;
        }
        // Stage pre-split W2 (64n x 64k): pure bf16 copies, 4 uint4/thread each.
        #pragma unroll
        for (int r = 0; r < 4; r++) {
            int idx8 = r * 128 + tid;
            int nl = idx8 >> 3;
            int k8 = (idx8 & 7) * 8;
            *(uint4*)&Whi[nl * 72 + k8] = *(const uint4*)&g_W2hi[(n0 + nl) * FEAT + k0 + k8];
            *(uint4*)&Wlo[nl * 72 + k8] = *(const uint4*)&g_W2lo[(n0 + nl) * FEAT + k0 + k8];
        }
        __syncthreads();

        #pragma unroll
        for (int kk = 0; kk < 64; kk += 16) {
            uint32_t ah[4][4], al[4][4], bh[2][2], bl[2][2];
            #pragma unroll
            for (int mt = 0; mt < 4; mt++) {
                uint32_t off = ((mt * 16 + arow) * 72 + kk + acolsel) * 2;
                ldm_x4(ah[mt], xhi_b + off);
                ldm_x4(al[mt], xlo_b + off);
            }
            #pragma unroll
            for (int nt = 0; nt < 2; nt++) {
                uint32_t off = ((nw + nt * 8 + brow) * 72 + kk + bcolsel) * 2;
                ldm_x2(bh[nt], whi_b + off);
                ldm_x2(bl[nt], wlo_b + off);
            }
            #pragma unroll
            for (int mt = 0; mt < 4; mt++)
                #pragma unroll
                for (int nt = 0; nt < 2; nt++) {
                    mma_bf16(acc[mt][nt], ah[mt], bh[nt]);
                    mma_bf16(acc[mt][nt], al[mt], bh[nt]);
                    mma_bf16(acc[mt][nt], ah[mt], bl[nt]);
                }
        }
    }

    int group = lane >> 2, tig = lane & 3;
    #pragma unroll
    for (int mt = 0; mt < 4; mt++)
        #pragma unroll
        for (int nt = 0; nt < 2; nt++) {
            int colb = n0 + nw + nt * 8 + tig * 2;
            int r0 = m0 + mt * 16 + group;
            int r1 = r0 + 8;
            if (r0 < NPAIR)
                *(float2*)&g_X2[r0 * FEAT + colb] = make_float2(acc[mt][nt][0], acc[mt][nt][1]);
            if (r1 < NPAIR)
                *(float2*)&g_X2[r1 * FEAT + colb] = make_float2(acc[mt][nt][2], acc[mt][nt][3]);
        }
}

// ---------------------------------------------------------------------------
// Kernel 3: ctx = (1/31) sum_p leaky(X2 + b2); w = ctx^4.
// Emits B' = [w | -2ws] as bf16 hi/lo rows [32][1280], plus Apart.
// grid (5 chunks, 32 classes), block 128.
// ---------------------------------------------------------------------------
__global__ void __launch_bounds__(128) ctx_prep_kernel(const float* __restrict__ S,
                                                       const float* __restrict__ b2) {
    __shared__ float rs[128];
    int i = blockIdx.y;
    int n = blockIdx.x * 128 + threadIdx.x;
    int tid = threadIdx.x;

    float bb = b2[n];
    float ssum = 0.f;
    int rbase = i * 31;
    #pragma unroll 4
    for (int p = 0; p < 31; p++)
        ssum += leaky(g_X2[(rbase + p) * FEAT + n] + bb);
    float ctx = ssum * (1.0f / 31.0f);
    float c2 = ctx * ctx;
    float w = c2 * c2;
    float s = S[i * FEAT + n];
    float nws2 = -2.0f * w * s;

    __nv_bfloat16 hi, lo;
    split1(w, hi, lo);
    g_Bhi[i * 2 * FEAT + n] = hi;
    g_Blo[i * 2 * FEAT + n] = lo;
    split1(nws2, hi, lo);
    g_Bhi[i * 2 * FEAT + FEAT + n] = hi;
    g_Blo[i * 2 * FEAT + FEAT + n] = lo;

    rs[tid] = w * s * s;
    __syncthreads();
    for (int st = 64; st > 0; st >>= 1) {
        if (tid < st) rs[tid] += rs[tid + st];
        __syncthreads();
    }
    if (tid == 0) g_Apart[blockIdx.x][i] = rs[0];
}

// ---------------------------------------------------------------------------
// Kernel 4 (mma.sync): dist partials. D = [Q^2 | Q] @ B'^T over K'=1280.
// grid (32 m-tiles of 128, DSPLIT=4), block 128 (4 warps).
// Warp tile 32m x 32n (2 mfrag x 4 nfrag). Each split's 320-col segment is
// purely Q^2 (ks<2) or purely Q (ks>=2). K chunks of 64.
// ---------------------------------------------------------------------------
__global__ void __launch_bounds__(128) dist_mma(const float* __restrict__ Q) {
    __shared__ __align__(16) __nv_bfloat16 Ahi[128 * 72], Alo[128 * 72];
    __shared__ __align__(16) __nv_bfloat16 Bh[32 * 72], Bl[32 * 72];

    int tid = threadIdx.x;
    int wid = tid >> 5, lane = tid & 31;
    int jb = blockIdx.x * 128;
    int ks = blockIdx.y;
    bool useq = (ks >= 2);
    int kbase = ks * DSEG;   // in A'-space [0,1280)

    uint32_t ahi_b = smem_u32(Ahi), alo_b = smem_u32(Alo);
    uint32_t bh_b = smem_u32(Bh), bl_b = smem_u32(Bl);

    float acc[2][4][4];
    #pragma unroll
    for (int a = 0; a < 2; a++)
        #pragma unroll
        for (int b = 0; b < 4; b++)
            #pragma unroll
            for (int cc = 0; cc < 4; cc++) acc[a][b][cc] = 0.f;

    int arow = lane & 15, acolsel = (lane >> 4) * 8;
    int brow = lane & 7,  bcolsel = ((lane >> 3) & 1) * 8;

    for (int c = 0; c < DSEG / 64; c++) {
        int kg = kbase + c * 64;               // A'-space
        int f0 = useq ? (kg - FEAT) : kg;      // feature offset into Q
        __syncthreads();
        // Stage A (128m x 64k): q or q^2, split hi/lo. 2048 float4, 16/thread.
        #pragma unroll
        for (int r = 0; r < 16; r++) {
            int idx4 = r * 128 + tid;
            int m  = idx4 >> 4;
            int k4 = (idx4 & 15) * 4;
            float4 v = *(const float4*)&Q[(jb + m) * FEAT + f0 + k4];
            if (!useq) { v.x *= v.x; v.y *= v.y; v.z *= v.z; v.w *= v.w; }
            uint2 hi, lo; split4(v, hi, lo);
            *(uint2*)&Ahi[m * 72 + k4] = hi;
            *(uint2*)&Alo[m * 72 + k4] = lo;
        }
        // Stage B (32n x 64k) from pre-split g_Bhi/g_Blo: 2 uint4/thread each.
        #pragma unroll
        for (int r = 0; r < 2; r++) {
            int idx8 = r * 128 + tid;
            int nl = idx8 >> 3;
            int k8 = (idx8 & 7) * 8;
            *(uint4*)&Bh[nl * 72 + k8] = *(const uint4*)&g_Bhi[nl * 2 * FEAT + kg + k8];
            *(uint4*)&Bl[nl * 72 + k8] = *(const uint4*)&g_Blo[nl * 2 * FEAT + kg + k8];
        }
        __syncthreads();

        #pragma unroll
        for (int kk = 0; kk < 64; kk += 16) {
            uint32_t ah[2][4], al[2][4], bh[4][2], bl[4][2];
            #pragma unroll
            for (int mt = 0; mt < 2; mt++) {
                uint32_t off = ((wid * 32 + mt * 16 + arow) * 72 + kk + acolsel) * 2;
                ldm_x4(ah[mt], ahi_b + off);
                ldm_x4(al[mt], alo_b + off);
            }
            #pragma unroll
            for (int nt = 0; nt < 4; nt++) {
                uint32_t off = ((nt * 8 + brow) * 72 + kk + bcolsel) * 2;
                ldm_x2(bh[nt], bh_b + off);
                ldm_x2(bl[nt], bl_b + off);
            }
            #pragma unroll
            for (int mt = 0; mt < 2; mt++)
                #pragma unroll
                for (int nt = 0; nt < 4; nt++) {
                    mma_bf16(acc[mt][nt], ah[mt], bh[nt]);
                    mma_bf16(acc[mt][nt], al[mt], bh[nt]);
                    mma_bf16(acc[mt][nt], ah[mt], bl[nt]);
                }
        }
    }

    float* P = g_P[ks];
    int group = lane >> 2, tig = lane & 3;
    #pragma unroll
    for (int mt = 0; mt < 2; mt++)
        #pragma unroll
        for (int nt = 0; nt < 4; nt++) {
            int col = nt * 8 + tig * 2;
            int r0 = jb + wid * 32 + mt * 16 + group;
            int r1 = r0 + 8;
            *(float2*)&P[r0 * WAY + col] = make_float2(acc[mt][nt][0], acc[mt][nt][1]);
            *(float2*)&P[r1 * WAY + col] = make_float2(acc[mt][nt][2], acc[mt][nt][3]);
        }
}

// ---------------------------------------------------------------------------
// Kernel 5: out[j,i] = -sqrt(max(A[i] + sum_ks P[ks][j,i], 0))
// ---------------------------------------------------------------------------
__global__ void finalize_kernel(float* __restrict__ out) {
    int gid = blockIdx.x * 256 + threadIdx.x;
    int base = gid * 4;
    float4 s = *(const float4*)&g_P[0][base];
    #pragma unroll
    for (int ks = 1; ks < DSPLIT; ks++) {
        float4 p = *(const float4*)&g_P[ks][base];
        s.x += p.x; s.y += p.y; s.z += p.z; s.w += p.w;
    }
    int i = base & 31;
    float4 a = *(const float4*)&g_Apart[0][i];
    #pragma unroll
    for (int c = 1; c < NCHUNK; c++) {
        float4 p = *(const float4*)&g_Apart[c][i];
        a.x += p.x; a.y += p.y; a.z += p.z; a.w += p.w;
    }
    float4 o;
    o.x = -sqrtf(fmaxf(a.x + s.x, 0.f));
    o.y = -sqrtf(fmaxf(a.y + s.y, 0.f));
    o.z = -sqrtf(fmaxf(a.z + s.z, 0.f));
    o.w = -sqrtf(fmaxf(a.w + s.w, 0.f));
    *(float4*)&out[base] = o;
}

// ---------------------------------------------------------------------------
extern "C" void kernel_launch(void* const* d_in, const int* in_sizes, int n_in,
                              void* d_out, int out_size) {
    const float* S  = (const float*)d_in[0];
    const float* Q  = (const float*)d_in[1];
    const float* W1 = (const float*)d_in[2];
    const float* b1 = (const float*)d_in[3];
    const float* W2 = (const float*)d_in[4];
    const float* b2 = (const float*)d_in[5];
    float* out = (float*)d_out;

    uv_kernel<<<160, 256>>>(S, W1, W2);
    gemm2_mma<<<dim3(MPAD / 64, FEAT / 64), 128>>>(b1);
    ctx_prep_kernel<<<dim3(NCHUNK, WAY), 128>>>(S, b2);
    dist_mma<<<dim3(NQ / 128, DSPLIT), 128>>>(Q);
    finalize_kernel<<<NQ * WAY / (256 * 4), 256>>>(out);
}

// round 14
// speedup vs baseline: 2.0608x; 1.2406x over previous
#include <cuda_runtime.h>
#include <cuda_bf16.h>
#include <math.h>
#include <stdint.h>

#define WAY  32
#define QRY  128
#define FEAT 640
#define NQ   (WAY*QRY)      // 4096
#define NPAIR (WAY*(WAY-1)) // 992
#define MPAD 1024

#define DSPLIT 10           // dist k-split (over K'=1280)
#define DSEG   128          // K' per split (2 chunks of 64)
#define NCHUNK 5            // ctx_prep n-chunks of 128

// Scratch (device globals; no allocation allowed)
__device__ __align__(16) float g_U[WAY*FEAT];
__device__ __align__(16) float g_V[WAY*FEAT];
__device__ __align__(16) float g_X2[NPAIR*FEAT];             // gemm2 result
__device__ __align__(16) __nv_bfloat16 g_X1hi[MPAD*FEAT];    // X1 bf16 hi
__device__ __align__(16) __nv_bfloat16 g_X1lo[MPAD*FEAT];    // X1 bf16 lo
__device__ __align__(16) __nv_bfloat16 g_W2hi[FEAT*FEAT];    // W2 bf16 hi
__device__ __align__(16) __nv_bfloat16 g_W2lo[FEAT*FEAT];    // W2 bf16 lo
__device__ __align__(16) __nv_bfloat16 g_Bhi[WAY*2*FEAT];    // [w | -2ws] hi
__device__ __align__(16) __nv_bfloat16 g_Blo[WAY*2*FEAT];    // [w | -2ws] lo
__device__ __align__(16) float g_Apart[NCHUNK][WAY];
__device__ __align__(16) float g_P[DSPLIT][NQ*WAY];          // distance partials

__device__ __forceinline__ float leaky(float x) { return x > 0.f ? x : 0.2f * x; }

__device__ __forceinline__ uint32_t smem_u32(const void* p) {
    uint32_t a;
    asm("{ .reg .u64 t; cvta.to.shared.u64 t, %1; cvt.u32.u64 %0, t; }" : "=r"(a) : "l"(p));
    return a;
}
__device__ __forceinline__ void ldm_x4(uint32_t* r, uint32_t addr) {
    asm volatile("ldmatrix.sync.aligned.m8n8.x4.shared.b16 {%0,%1,%2,%3}, [%4];"
                 : "=r"(r[0]), "=r"(r[1]), "=r"(r[2]), "=r"(r[3]) : "r"(addr));
}
__device__ __forceinline__ void ldm_x2(uint32_t* r, uint32_t addr) {
    asm volatile("ldmatrix.sync.aligned.m8n8.x2.shared.b16 {%0,%1}, [%2];"
                 : "=r"(r[0]), "=r"(r[1]) : "r"(addr));
}
__device__ __forceinline__ void mma_bf16(float* c, const uint32_t* a, const uint32_t* b) {
    asm volatile(
        "mma.sync.aligned.m16n8k16.row.col.f32.bf16.bf16.f32 "
        "{%0,%1,%2,%3}, {%4,%5,%6,%7}, {%8,%9}, {%0,%1,%2,%3};"
        : "+f"(c[0]), "+f"(c[1]), "+f"(c[2]), "+f"(c[3])
        : "r"(a[0]), "r"(a[1]), "r"(a[2]), "r"(a[3]), "r"(b[0]), "r"(b[1]));
}
// Truncation-based hi/lo split: hi = high 16 bits, lo = trunc(v - hi). Cheap.
__device__ __forceinline__ void split4t(float4 v, uint2& hi, uint2& lo) {
    uint32_t ux = __float_as_uint(v.x), uy = __float_as_uint(v.y),
             uz = __float_as_uint(v.z), uw = __float_as_uint(v.w);
    float rx = v.x - __uint_as_float(ux & 0xFFFF0000u);
    float ry = v.y - __uint_as_float(uy & 0xFFFF0000u);
    float rz = v.z - __uint_as_float(uz & 0xFFFF0000u);
    float rw = v.w - __uint_as_float(uw & 0xFFFF0000u);
    hi.x = __byte_perm(ux, uy, 0x7632);
    hi.y = __byte_perm(uz, uw, 0x7632);
    lo.x = __byte_perm(__float_as_uint(rx), __float_as_uint(ry), 0x7632);
    lo.y = __byte_perm(__float_as_uint(rz), __float_as_uint(rw), 0x7632);
}
__device__ __forceinline__ void split1(float v, __nv_bfloat16& hi, __nv_bfloat16& lo) {
    hi = __float2bfloat16(v);
    lo = __float2bfloat16(v - __bfloat162float(hi));
}

// ---------------------------------------------------------------------------
// Kernel 1: U = S @ W1[:, :640]^T, V = S @ W1[:, 640:]^T; tail: split W2->bf16.
// ---------------------------------------------------------------------------
__global__ void uv_kernel(const float* __restrict__ S, const float* __restrict__ W1,
                          const float* __restrict__ W2) {
    __shared__ float St[320 * 33];
    int tid = threadIdx.x;
    int c = blockIdx.x * 8 + (tid >> 5);
    int i = tid & 31;
    int half = (c >= FEAT) ? 1 : 0;
    int o = c - half * FEAT;
    const float* w1row = W1 + o * (2 * FEAT) + half * FEAT;

    float a0 = 0.f, a1 = 0.f, a2 = 0.f, a3 = 0.f;
    for (int k0 = 0; k0 < FEAT; k0 += 320) {
        __syncthreads();
        #pragma unroll
        for (int r = 0; r < 10; r++) {
            int idx4 = r * 256 + tid;
            int ii = idx4 / 80;
            int kk4 = (idx4 - ii * 80) * 4;
            float4 v = *(const float4*)&S[ii * FEAT + k0 + kk4];
            St[(kk4 + 0) * 33 + ii] = v.x;
            St[(kk4 + 1) * 33 + ii] = v.y;
            St[(kk4 + 2) * 33 + ii] = v.z;
            St[(kk4 + 3) * 33 + ii] = v.w;
        }
        __syncthreads();
        #pragma unroll 4
        for (int kk = 0; kk < 320; kk += 4) {
            float4 wv = *(const float4*)&w1row[k0 + kk];
            a0 = fmaf(St[(kk + 0) * 33 + i], wv.x, a0);
            a1 = fmaf(St[(kk + 1) * 33 + i], wv.y, a1);
            a2 = fmaf(St[(kk + 2) * 33 + i], wv.z, a2);
            a3 = fmaf(St[(kk + 3) * 33 + i], wv.w, a3);
        }
    }
    float acc = (a0 + a1) + (a2 + a3);
    if (half) g_V[i * FEAT + o] = acc;
    else      g_U[i * FEAT + o] = acc;

    // Tail: W2 fp32 -> bf16 hi/lo (grid-stride).
    int nthr = gridDim.x * blockDim.x;
    for (int idx4 = blockIdx.x * blockDim.x + tid; idx4 < FEAT * FEAT / 4; idx4 += nthr) {
        float4 v = *(const float4*)&W2[idx4 * 4];
        uint2 hi, lo; split4t(v, hi, lo);
        *(uint2*)&g_W2hi[idx4 * 4] = hi;
        *(uint2*)&g_W2lo[idx4 * 4] = lo;
    }
}

// ---------------------------------------------------------------------------
// Kernel 1b: X1 = leaky(U + V + b1) -> bf16 hi/lo, once. grid 640, block 256.
// ---------------------------------------------------------------------------
__global__ void __launch_bounds__(256) x1split_kernel(const float* __restrict__ b1) {
    int idx4 = blockIdx.x * 256 + threadIdx.x;   // 0..163839 (1024 rows x 160)
    int row = idx4 / 160;
    int k4 = (idx4 - row * 160) * 4;
    float4 v;
    if (row < NPAIR) {
        int i = row / 31;
        int p = row - i * 31;
        int j = (p < i) ? p : p + 1;
        float4 u4 = *(const float4*)&g_U[i * FEAT + k4];
        float4 v4 = *(const float4*)&g_V[j * FEAT + k4];
        float4 b4 = *(const float4*)&b1[k4];
        v.x = leaky(u4.x + v4.x + b4.x);
        v.y = leaky(u4.y + v4.y + b4.y);
        v.z = leaky(u4.z + v4.z + b4.z);
        v.w = leaky(u4.w + v4.w + b4.w);
    } else v = make_float4(0.f, 0.f, 0.f, 0.f);
    uint2 hi, lo; split4t(v, hi, lo);
    *(uint2*)&g_X1hi[row * FEAT + k4] = hi;
    *(uint2*)&g_X1lo[row * FEAT + k4] = lo;
}

// ---------------------------------------------------------------------------
// Kernel 2 (mma.sync): X2 = X1 @ W2^T. Pre-split bf16 inputs, pure copies in.
// grid (16 m-tiles, 10 n-tiles), block 256 (8 warps). Block 64m x 64n,
// warp 16m x 32n. K chunks of 64. Smem row stride 72 bf16.
// ---------------------------------------------------------------------------
__global__ void __launch_bounds__(256) gemm2_mma() {
    __shared__ __align__(16) __nv_bfloat16 Xhi[64 * 72], Xlo[64 * 72];
    __shared__ __align__(16) __nv_bfloat16 Whi[64 * 72], Wlo[64 * 72];

    int tid = threadIdx.x;
    int wid = tid >> 5, lane = tid & 31;
    int m0 = blockIdx.x * 64, n0 = blockIdx.y * 64;
    int wm = wid >> 1, wn = wid & 1;      // warp: rows wm*16, cols wn*32

    uint32_t xhi_b = smem_u32(Xhi), xlo_b = smem_u32(Xlo);
    uint32_t whi_b = smem_u32(Whi), wlo_b = smem_u32(Wlo);

    float acc[4][4];
    #pragma unroll
    for (int a = 0; a < 4; a++)
        #pragma unroll
        for (int b = 0; b < 4; b++) acc[a][b] = 0.f;

    int arow = lane & 15, acolsel = (lane >> 4) * 8;
    int brow = lane & 7,  bcolsel = ((lane >> 3) & 1) * 8;

    for (int c = 0; c < 10; c++) {
        int k0 = c * 64;
        __syncthreads();
        // X tile (64m x 64k) + W tile (64n x 64k): bf16 uint4 copies, 2/thread each.
        #pragma unroll
        for (int r = 0; r < 2; r++) {
            int idx8 = r * 256 + tid;
            int rl = idx8 >> 3;
            int k8 = (idx8 & 7) * 8;
            *(uint4*)&Xhi[rl * 72 + k8] = *(const uint4*)&g_X1hi[(m0 + rl) * FEAT + k0 + k8];
            *(uint4*)&Xlo[rl * 72 + k8] = *(const uint4*)&g_X1lo[(m0 + rl) * FEAT + k0 + k8];
            *(uint4*)&Whi[rl * 72 + k8] = *(const uint4*)&g_W2hi[(n0 + rl) * FEAT + k0 + k8];
            *(uint4*)&Wlo[rl * 72 + k8] = *(const uint4*)&g_W2lo[(n0 + rl) * FEAT + k0 + k8];
        }
        __syncthreads();

        #pragma unroll
        for (int kk = 0; kk < 64; kk += 16) {
            uint32_t ah[4], al[4], bh[4][2], bl[4][2];
            uint32_t aoff = ((wm * 16 + arow) * 72 + kk + acolsel) * 2;
            ldm_x4(ah, xhi_b + aoff);
            ldm_x4(al, xlo_b + aoff);
            #pragma unroll
            for (int nt = 0; nt < 4; nt++) {
                uint32_t off = ((wn * 32 + nt * 8 + brow) * 72 + kk + bcolsel) * 2;
                ldm_x2(bh[nt], whi_b + off);
                ldm_x2(bl[nt], wlo_b + off);
            }
            #pragma unroll
            for (int nt = 0; nt < 4; nt++) {
                mma_bf16(acc[nt], ah, bh[nt]);
                mma_bf16(acc[nt], al, bh[nt]);
                mma_bf16(acc[nt], ah, bl[nt]);
            }
        }
    }

    int group = lane >> 2, tig = lane & 3;
    #pragma unroll
    for (int nt = 0; nt < 4; nt++) {
        int colb = n0 + wn * 32 + nt * 8 + tig * 2;
        int r0 = m0 + wm * 16 + group;
        int r1 = r0 + 8;
        if (r0 < NPAIR)
            *(float2*)&g_X2[r0 * FEAT + colb] = make_float2(acc[nt][0], acc[nt][1]);
        if (r1 < NPAIR)
            *(float2*)&g_X2[r1 * FEAT + colb] = make_float2(acc[nt][2], acc[nt][3]);
    }
}

// ---------------------------------------------------------------------------
// Kernel 3: ctx = (1/31) sum_p leaky(X2 + b2); w = ctx^4.
// Emits B' = [w | -2ws] bf16 hi/lo rows [32][1280], plus Apart.
// ---------------------------------------------------------------------------
__global__ void __launch_bounds__(128) ctx_prep_kernel(const float* __restrict__ S,
                                                       const float* __restrict__ b2) {
    __shared__ float rs[128];
    int i = blockIdx.y;
    int n = blockIdx.x * 128 + threadIdx.x;
    int tid = threadIdx.x;

    float bb = b2[n];
    float ssum = 0.f;
    int rbase = i * 31;
    #pragma unroll 4
    for (int p = 0; p < 31; p++)
        ssum += leaky(g_X2[(rbase + p) * FEAT + n] + bb);
    float ctx = ssum * (1.0f / 31.0f);
    float c2 = ctx * ctx;
    float w = c2 * c2;
    float s = S[i * FEAT + n];
    float nws2 = -2.0f * w * s;

    __nv_bfloat16 hi, lo;
    split1(w, hi, lo);
    g_Bhi[i * 2 * FEAT + n] = hi;
    g_Blo[i * 2 * FEAT + n] = lo;
    split1(nws2, hi, lo);
    g_Bhi[i * 2 * FEAT + FEAT + n] = hi;
    g_Blo[i * 2 * FEAT + FEAT + n] = lo;

    rs[tid] = w * s * s;
    __syncthreads();
    for (int st = 64; st > 0; st >>= 1) {
        if (tid < st) rs[tid] += rs[tid + st];
        __syncthreads();
    }
    if (tid == 0) g_Apart[blockIdx.x][i] = rs[0];
}

// ---------------------------------------------------------------------------
// Kernel 4 (mma.sync): dist partials. D = [Q^2 | Q] @ B'^T over K'=1280.
// grid (32 m-tiles of 128, DSPLIT=10), block 256 (8 warps).
// Warp tile 16m x 32n. Segment is purely Q^2 (ks<5) or Q (ks>=5).
// ---------------------------------------------------------------------------
__global__ void __launch_bounds__(256) dist_mma(const float* __restrict__ Q) {
    __shared__ __align__(16) __nv_bfloat16 Ahi[128 * 72], Alo[128 * 72];
    __shared__ __align__(16) __nv_bfloat16 Bh[32 * 72], Bl[32 * 72];

    int tid = threadIdx.x;
    int wid = tid >> 5, lane = tid & 31;
    int jb = blockIdx.x * 128;
    int ks = blockIdx.y;
    bool useq = (ks >= 5);
    int kbase = ks * DSEG;

    uint32_t ahi_b = smem_u32(Ahi), alo_b = smem_u32(Alo);
    uint32_t bh_b = smem_u32(Bh), bl_b = smem_u32(Bl);

    float acc[4][4];
    #pragma unroll
    for (int a = 0; a < 4; a++)
        #pragma unroll
        for (int b = 0; b < 4; b++) acc[a][b] = 0.f;

    int arow = lane & 15, acolsel = (lane >> 4) * 8;
    int brow = lane & 7,  bcolsel = ((lane >> 3) & 1) * 8;

    #pragma unroll
    for (int c = 0; c < 2; c++) {
        int kg = kbase + c * 64;
        int f0 = useq ? (kg - FEAT) : kg;
        __syncthreads();
        // A (128m x 64k): load fp32, optional square, trunc-split. 8 float4/thread.
        #pragma unroll
        for (int r = 0; r < 8; r++) {
            int idx4 = r * 256 + tid;
            int m  = idx4 >> 4;
            int k4 = (idx4 & 15) * 4;
            float4 v = *(const float4*)&Q[(jb + m) * FEAT + f0 + k4];
            if (!useq) { v.x *= v.x; v.y *= v.y; v.z *= v.z; v.w *= v.w; }
            uint2 hi, lo; split4t(v, hi, lo);
            *(uint2*)&Ahi[m * 72 + k4] = hi;
            *(uint2*)&Alo[m * 72 + k4] = lo;
        }
        // B (32n x 64k): bf16 copies, 1 uint4/thread each.
        {
            int nl = tid >> 3;
            int k8 = (tid & 7) * 8;
            *(uint4*)&Bh[nl * 72 + k8] = *(const uint4*)&g_Bhi[nl * 2 * FEAT + kg + k8];
            *(uint4*)&Bl[nl * 72 + k8] = *(const uint4*)&g_Blo[nl * 2 * FEAT + kg + k8];
        }
        __syncthreads();

        #pragma unroll
        for (int kk = 0; kk < 64; kk += 16) {
            uint32_t ah[4], al[4], bh[4][2], bl[4][2];
            uint32_t aoff = ((wid * 16 + arow) * 72 + kk + acolsel) * 2;
            ldm_x4(ah, ahi_b + aoff);
            ldm_x4(al, alo_b + aoff);
            #pragma unroll
            for (int nt = 0; nt < 4; nt++) {
                uint32_t off = ((nt * 8 + brow) * 72 + kk + bcolsel) * 2;
                ldm_x2(bh[nt], bh_b + off);
                ldm_x2(bl[nt], bl_b + off);
            }
            #pragma unroll
            for (int nt = 0; nt < 4; nt++) {
                mma_bf16(acc[nt], ah, bh[nt]);
                mma_bf16(acc[nt], al, bh[nt]);
                mma_bf16(acc[nt], ah, bl[nt]);
            }
        }
    }

    float* P = g_P[ks];
    int group = lane >> 2, tig = lane & 3;
    #pragma unroll
    for (int nt = 0; nt < 4; nt++) {
        int col = nt * 8 + tig * 2;
        int r0 = jb + wid * 16 + group;
        int r1 = r0 + 8;
        *(float2*)&P[r0 * WAY + col] = make_float2(acc[nt][0], acc[nt][1]);
        *(float2*)&P[r1 * WAY + col] = make_float2(acc[nt][2], acc[nt][3]);
    }
}

// ---------------------------------------------------------------------------
// Kernel 5: out[j,i] = -sqrt(max(A[i] + sum_ks P[ks][j,i], 0))
// ---------------------------------------------------------------------------
__global__ void finalize_kernel(float* __restrict__ out) {
    int gid = blockIdx.x * 256 + threadIdx.x;
    int base = gid * 4;
    float4 s = *(const float4*)&g_P[0][base];
    #pragma unroll
    for (int ks = 1; ks < DSPLIT; ks++) {
        float4 p = *(const float4*)&g_P[ks][base];
        s.x += p.x; s.y += p.y; s.z += p.z; s.w += p.w;
    }
    int i = base & 31;
    float4 a = *(const float4*)&g_Apart[0][i];
    #pragma unroll
    for (int c = 1; c < NCHUNK; c++) {
        float4 p = *(const float4*)&g_Apart[c][i];
        a.x += p.x; a.y += p.y; a.z += p.z; a.w += p.w;
    }
    float4 o;
    o.x = -sqrtf(fmaxf(a.x + s.x, 0.f));
    o.y = -sqrtf(fmaxf(a.y + s.y, 0.f));
    o.z = -sqrtf(fmaxf(a.z + s.z, 0.f));
    o.w = -sqrtf(fmaxf(a.w + s.w, 0.f));
    *(float4*)&out[base] = o;
}

// ---------------------------------------------------------------------------
extern "C" void kernel_launch(void* const* d_in, const int* in_sizes, int n_in,
                              void* d_out, int out_size) {
    const float* S  = (const float*)d_in[0];
    const float* Q  = (const float*)d_in[1];
    const float* W1 = (const float*)d_in[2];
    const float* b1 = (const float*)d_in[3];
    const float* W2 = (const float*)d_in[4];
    const float* b2 = (const float*)d_in[5];
    float* out = (float*)d_out;

    uv_kernel<<<160, 256>>>(S, W1, W2);
    x1split_kernel<<<MPAD * FEAT / 4 / 256, 256>>>(b1);
    gemm2_mma<<<dim3(MPAD / 64, FEAT / 64), 256>>>();
    ctx_prep_kernel<<<dim3(NCHUNK, WAY), 128>>>(S, b2);
    dist_mma<<<dim3(NQ / 128, DSPLIT), 256>>>(Q);
    finalize_kernel<<<NQ * WAY / (256 * 4), 256>>>(out);
}

// round 15
// speedup vs baseline: 2.0619x; 1.0005x over previous
#include <cuda_runtime.h>
#include <cuda_bf16.h>
#include <math.h>
#include <stdint.h>

#define WAY  32
#define QRY  128
#define FEAT 640
#define NQ   (WAY*QRY)      // 4096
#define NPAIR (WAY*(WAY-1)) // 992
#define MPAD 1024

#define DSPLIT 10           // dist k-split (over K'=1280)
#define DSEG   128          // K' per split (2 chunks of 64)
#define NCHUNK 5            // ctx_prep n-chunks of 128

// Scratch (device globals; no allocation allowed)
__device__ __align__(16) float g_U[WAY*FEAT];
__device__ __align__(16) float g_V[WAY*FEAT];
__device__ __align__(16) float g_X2[NPAIR*FEAT];             // gemm2 result
__device__ __align__(16) __nv_bfloat16 g_X1hi[MPAD*FEAT];    // X1 bf16 hi
__device__ __align__(16) __nv_bfloat16 g_X1lo[MPAD*FEAT];    // X1 bf16 lo
__device__ __align__(16) __nv_bfloat16 g_W2hi[FEAT*FEAT];    // W2 bf16 hi
__device__ __align__(16) __nv_bfloat16 g_W2lo[FEAT*FEAT];    // W2 bf16 lo
__device__ __align__(16) __nv_bfloat16 g_Bhi[WAY*2*FEAT];    // [w | -2ws] hi
__device__ __align__(16) __nv_bfloat16 g_Blo[WAY*2*FEAT];    // [w | -2ws] lo
__device__ __align__(16) float g_Apart[NCHUNK][WAY];
__device__ __align__(16) float g_P[DSPLIT][NQ*WAY];          // distance partials

__device__ __forceinline__ float leaky(float x) { return x > 0.f ? x : 0.2f * x; }

__device__ __forceinline__ uint32_t smem_u32(const void* p) {
    uint32_t a;
    asm("{ .reg .u64 t; cvta.to.shared.u64 t, %1; cvt.u32.u64 %0, t; }" : "=r"(a) : "l"(p));
    return a;
}
__device__ __forceinline__ void ldm_x4(uint32_t* r, uint32_t addr) {
    asm volatile("ldmatrix.sync.aligned.m8n8.x4.shared.b16 {%0,%1,%2,%3}, [%4];"
                 : "=r"(r[0]), "=r"(r[1]), "=r"(r[2]), "=r"(r[3]) : "r"(addr));
}
__device__ __forceinline__ void ldm_x2(uint32_t* r, uint32_t addr) {
    asm volatile("ldmatrix.sync.aligned.m8n8.x2.shared.b16 {%0,%1}, [%2];"
                 : "=r"(r[0]), "=r"(r[1]) : "r"(addr));
}
__device__ __forceinline__ void mma_bf16(float* c, const uint32_t* a, const uint32_t* b) {
    asm volatile(
        "mma.sync.aligned.m16n8k16.row.col.f32.bf16.bf16.f32 "
        "{%0,%1,%2,%3}, {%4,%5,%6,%7}, {%8,%9}, {%0,%1,%2,%3};"
        : "+f"(c[0]), "+f"(c[1]), "+f"(c[2]), "+f"(c[3])
        : "r"(a[0]), "r"(a[1]), "r"(a[2]), "r"(a[3]), "r"(b[0]), "r"(b[1]));
}
// Truncation-based hi/lo split: hi = high 16 bits, lo = trunc(v - hi). Cheap.
__device__ __forceinline__ void split4t(float4 v, uint2& hi, uint2& lo) {
    uint32_t ux = __float_as_uint(v.x), uy = __float_as_uint(v.y),
             uz = __float_as_uint(v.z), uw = __float_as_uint(v.w);
    float rx = v.x - __uint_as_float(ux & 0xFFFF0000u);
    float ry = v.y - __uint_as_float(uy & 0xFFFF0000u);
    float rz = v.z - __uint_as_float(uz & 0xFFFF0000u);
    float rw = v.w - __uint_as_float(uw & 0xFFFF0000u);
    hi.x = __byte_perm(ux, uy, 0x7632);
    hi.y = __byte_perm(uz, uw, 0x7632);
    lo.x = __byte_perm(__float_as_uint(rx), __float_as_uint(ry), 0x7632);
    lo.y = __byte_perm(__float_as_uint(rz), __float_as_uint(rw), 0x7632);
}
__device__ __forceinline__ void split1(float v, __nv_bfloat16& hi, __nv_bfloat16& lo) {
    hi = __float2bfloat16(v);
    lo = __float2bfloat16(v - __bfloat162float(hi));
}

// ---------------------------------------------------------------------------
// Kernel 1: U = S @ W1[:, :640]^T, V = S @ W1[:, 640:]^T; tail: split W2->bf16.
// ---------------------------------------------------------------------------
__global__ void uv_kernel(const float* __restrict__ S, const float* __restrict__ W1,
                          const float* __restrict__ W2) {
    __shared__ float St[320 * 33];
    int tid = threadIdx.x;
    int c = blockIdx.x * 8 + (tid >> 5);
    int i = tid & 31;
    int half = (c >= FEAT) ? 1 : 0;
    int o = c - half * FEAT;
    const float* w1row = W1 + o * (2 * FEAT) + half * FEAT;

    float a0 = 0.f, a1 = 0.f, a2 = 0.f, a3 = 0.f;
    for (int k0 = 0; k0 < FEAT; k0 += 320) {
        __syncthreads();
        #pragma unroll
        for (int r = 0; r < 10; r++) {
            int idx4 = r * 256 + tid;
            int ii = idx4 / 80;
            int kk4 = (idx4 - ii * 80) * 4;
            float4 v = *(const float4*)&S[ii * FEAT + k0 + kk4];
            St[(kk4 + 0) * 33 + ii] = v.x;
            St[(kk4 + 1) * 33 + ii] = v.y;
            St[(kk4 + 2) * 33 + ii] = v.z;
            St[(kk4 + 3) * 33 + ii] = v.w;
        }
        __syncthreads();
        #pragma unroll 4
        for (int kk = 0; kk < 320; kk += 4) {
            float4 wv = *(const float4*)&w1row[k0 + kk];
            a0 = fmaf(St[(kk + 0) * 33 + i], wv.x, a0);
            a1 = fmaf(St[(kk + 1) * 33 + i], wv.y, a1);
            a2 = fmaf(St[(kk + 2) * 33 + i], wv.z, a2);
            a3 = fmaf(St[(kk + 3) * 33 + i], wv.w, a3);
        }
    }
    float acc = (a0 + a1) + (a2 + a3);
    if (half) g_V[i * FEAT + o] = acc;
    else      g_U[i * FEAT + o] = acc;

    // Tail: W2 fp32 -> bf16 hi/lo (grid-stride).
    int nthr = gridDim.x * blockDim.x;
    for (int idx4 = blockIdx.x * blockDim.x + tid; idx4 < FEAT * FEAT / 4; idx4 += nthr) {
        float4 v = *(const float4*)&W2[idx4 * 4];
        uint2 hi, lo; split4t(v, hi, lo);
        *(uint2*)&g_W2hi[idx4 * 4] = hi;
        *(uint2*)&g_W2lo[idx4 * 4] = lo;
    }
}

// ---------------------------------------------------------------------------
// Kernel 1b: X1 = leaky(U + V + b1) -> bf16 hi/lo, once. grid 640, block 256.
// ---------------------------------------------------------------------------
__global__ void __launch_bounds__(256) x1split_kernel(const float* __restrict__ b1) {
    int idx4 = blockIdx.x * 256 + threadIdx.x;   // 0..163839 (1024 rows x 160)
    int row = idx4 / 160;
    int k4 = (idx4 - row * 160) * 4;
    float4 v;
    if (row < NPAIR) {
        int i = row / 31;
        int p = row - i * 31;
        int j = (p < i) ? p : p + 1;
        float4 u4 = *(const float4*)&g_U[i * FEAT + k4];
        float4 v4 = *(const float4*)&g_V[j * FEAT + k4];
        float4 b4 = *(const float4*)&b1[k4];
        v.x = leaky(u4.x + v4.x + b4.x);
        v.y = leaky(u4.y + v4.y + b4.y);
        v.z = leaky(u4.z + v4.z + b4.z);
        v.w = leaky(u4.w + v4.w + b4.w);
    } else v = make_float4(0.f, 0.f, 0.f, 0.f);
    uint2 hi, lo; split4t(v, hi, lo);
    *(uint2*)&g_X1hi[row * FEAT + k4] = hi;
    *(uint2*)&g_X1lo[row * FEAT + k4] = lo;
}

// ---------------------------------------------------------------------------
// Kernel 2 (mma.sync): X2 = X1 @ W2^T. Pre-split bf16 inputs, pure copies in.
// grid (16 m-tiles, 10 n-tiles), block 256 (8 warps). Block 64m x 64n,
// warp 16m x 32n. K chunks of 64. Smem row stride 72 bf16.
// ---------------------------------------------------------------------------
__global__ void __launch_bounds__(256) gemm2_mma() {
    __shared__ __align__(16) __nv_bfloat16 Xhi[64 * 72], Xlo[64 * 72];
    __shared__ __align__(16) __nv_bfloat16 Whi[64 * 72], Wlo[64 * 72];

    int tid = threadIdx.x;
    int wid = tid >> 5, lane = tid & 31;
    int m0 = blockIdx.x * 64, n0 = blockIdx.y * 64;
    int wm = wid >> 1, wn = wid & 1;      // warp: rows wm*16, cols wn*32

    uint32_t xhi_b = smem_u32(Xhi), xlo_b = smem_u32(Xlo);
    uint32_t whi_b = smem_u32(Whi), wlo_b = smem_u32(Wlo);

    float acc[4][4];
    #pragma unroll
    for (int a = 0; a < 4; a++)
        #pragma unroll
        for (int b = 0; b < 4; b++) acc[a][b] = 0.f;

    int arow = lane & 15, acolsel = (lane >> 4) * 8;
    int brow = lane & 7,  bcolsel = ((lane >> 3) & 1) * 8;

    for (int c = 0; c < 10; c++) {
        int k0 = c * 64;
        __syncthreads();
        // X tile (64m x 64k) + W tile (64n x 64k): bf16 uint4 copies, 2/thread each.
        #pragma unroll
        for (int r = 0; r < 2; r++) {
            int idx8 = r * 256 + tid;
            int rl = idx8 >> 3;
            int k8 = (idx8 & 7) * 8;
            *(uint4*)&Xhi[rl * 72 + k8] = *(const uint4*)&g_X1hi[(m0 + rl) * FEAT + k0 + k8];
            *(uint4*)&Xlo[rl * 72 + k8] = *(const uint4*)&g_X1lo[(m0 + rl) * FEAT + k0 + k8];
            *(uint4*)&Whi[rl * 72 + k8] = *(const uint4*)&g_W2hi[(n0 + rl) * FEAT + k0 + k8];
            *(uint4*)&Wlo[rl * 72 + k8] = *(const uint4*)&g_W2lo[(n0 + rl) * FEAT + k0 + k8];
        }
        __syncthreads();

        #pragma unroll
        for (int kk = 0; kk < 64; kk += 16) {
            uint32_t ah[4], al[4], bh[4][2], bl[4][2];
            uint32_t aoff = ((wm * 16 + arow) * 72 + kk + acolsel) * 2;
            ldm_x4(ah, xhi_b + aoff);
            ldm_x4(al, xlo_b + aoff);
            #pragma unroll
            for (int nt = 0; nt < 4; nt++) {
                uint32_t off = ((wn * 32 + nt * 8 + brow) * 72 + kk + bcolsel) * 2;
                ldm_x2(bh[nt], whi_b + off);
                ldm_x2(bl[nt], wlo_b + off);
            }
            #pragma unroll
            for (int nt = 0; nt < 4; nt++) {
                mma_bf16(acc[nt], ah, bh[nt]);
                mma_bf16(acc[nt], al, bh[nt]);
                mma_bf16(acc[nt], ah, bl[nt]);
            }
        }
    }

    int group = lane >> 2, tig = lane & 3;
    #pragma unroll
    for (int nt = 0; nt < 4; nt++) {
        int colb = n0 + wn * 32 + nt * 8 + tig * 2;
        int r0 = m0 + wm * 16 + group;
        int r1 = r0 + 8;
        if (r0 < NPAIR)
            *(float2*)&g_X2[r0 * FEAT + colb] = make_float2(acc[nt][0], acc[nt][1]);
        if (r1 < NPAIR)
            *(float2*)&g_X2[r1 * FEAT + colb] = make_float2(acc[nt][2], acc[nt][3]);
    }
}

// ---------------------------------------------------------------------------
// Kernel 3: ctx = (1/31) sum_p leaky(X2 + b2); w = ctx^4.
// Emits B' = [w | -2ws] bf16 hi/lo rows [32][1280], plus Apart.
// grid (5 chunks, 32 classes), block (128 n, 4 p-groups) = 512 threads.
// Each thread sums 8 of 31 pair-rows fully unrolled (8 loads in flight),
// then 4-way p-combine + 128-wide A-reduction in smem.
// ---------------------------------------------------------------------------
__global__ void __launch_bounds__(512) ctx_prep_kernel(const float* __restrict__ S,
                                                       const float* __restrict__ b2) {
    __shared__ float red[4][128];
    __shared__ float rs[128];
    int tx = threadIdx.x;   // n within chunk
    int ty = threadIdx.y;   // p-group
    int flat = ty * 128 + tx;
    int i = blockIdx.y;
    int n = blockIdx.x * 128 + tx;

    float bb = b2[n];
    int rbase = i * 31;
    int p0 = ty * 8;
    float ssum = 0.f;
    #pragma unroll
    for (int pp = 0; pp < 8; pp++) {
        int p = p0 + pp;
        if (p < 31)
            ssum += leaky(__ldg(&g_X2[(rbase + p) * FEAT + n]) + bb);
    }
    red[ty][tx] = ssum;
    __syncthreads();

    if (ty == 0) {
        float s31 = (red[0][tx] + red[1][tx]) + (red[2][tx] + red[3][tx]);
        float ctx = s31 * (1.0f / 31.0f);
        float c2 = ctx * ctx;
        float w = c2 * c2;
        float s = S[i * FEAT + n];
        float nws2 = -2.0f * w * s;

        __nv_bfloat16 hi, lo;
        split1(w, hi, lo);
        g_Bhi[i * 2 * FEAT + n] = hi;
        g_Blo[i * 2 * FEAT + n] = lo;
        split1(nws2, hi, lo);
        g_Bhi[i * 2 * FEAT + FEAT + n] = hi;
        g_Blo[i * 2 * FEAT + FEAT + n] = lo;

        rs[tx] = w * s * s;
    }
    __syncthreads();
    for (int st = 64; st > 0; st >>= 1) {
        if (flat < st) rs[flat] += rs[flat + st];
        __syncthreads();
    }
    if (flat == 0) g_Apart[blockIdx.x][i] = rs[0];
}

// ---------------------------------------------------------------------------
// Kernel 4 (mma.sync): dist partials. D = [Q^2 | Q] @ B'^T over K'=1280.
// grid (32 m-tiles of 128, DSPLIT=10), block 256 (8 warps).
// Warp tile 16m x 32n. Segment is purely Q^2 (ks<5) or Q (ks>=5).
// ---------------------------------------------------------------------------
__global__ void __launch_bounds__(256) dist_mma(const float* __restrict__ Q) {
    __shared__ __align__(16) __nv_bfloat16 Ahi[128 * 72], Alo[128 * 72];
    __shared__ __align__(16) __nv_bfloat16 Bh[32 * 72], Bl[32 * 72];

    int tid = threadIdx.x;
    int wid = tid >> 5, lane = tid & 31;
    int jb = blockIdx.x * 128;
    int ks = blockIdx.y;
    bool useq = (ks >= 5);
    int kbase = ks * DSEG;

    uint32_t ahi_b = smem_u32(Ahi), alo_b = smem_u32(Alo);
    uint32_t bh_b = smem_u32(Bh), bl_b = smem_u32(Bl);

    float acc[4][4];
    #pragma unroll
    for (int a = 0; a < 4; a++)
        #pragma unroll
        for (int b = 0; b < 4; b++) acc[a][b] = 0.f;

    int arow = lane & 15, acolsel = (lane >> 4) * 8;
    int brow = lane & 7,  bcolsel = ((lane >> 3) & 1) * 8;

    #pragma unroll
    for (int c = 0; c < 2; c++) {
        int kg = kbase + c * 64;
        int f0 = useq ? (kg - FEAT) : kg;
        __syncthreads();
        // A (128m x 64k): load fp32, optional square, trunc-split. 8 float4/thread.
        #pragma unroll
        for (int r = 0; r < 8; r++) {
            int idx4 = r * 256 + tid;
            int m  = idx4 >> 4;
            int k4 = (idx4 & 15) * 4;
            float4 v = *(const float4*)&Q[(jb + m) * FEAT + f0 + k4];
            if (!useq) { v.x *= v.x; v.y *= v.y; v.z *= v.z; v.w *= v.w; }
            uint2 hi, lo; split4t(v, hi, lo);
            *(uint2*)&Ahi[m * 72 + k4] = hi;
            *(uint2*)&Alo[m * 72 + k4] = lo;
        }
        // B (32n x 64k): bf16 copies, 1 uint4/thread each.
        {
            int nl = tid >> 3;
            int k8 = (tid & 7) * 8;
            *(uint4*)&Bh[nl * 72 + k8] = *(const uint4*)&g_Bhi[nl * 2 * FEAT + kg + k8];
            *(uint4*)&Bl[nl * 72 + k8] = *(const uint4*)&g_Blo[nl * 2 * FEAT + kg + k8];
        }
        __syncthreads();

        #pragma unroll
        for (int kk = 0; kk < 64; kk += 16) {
            uint32_t ah[4], al[4], bh[4][2], bl[4][2];
            uint32_t aoff = ((wid * 16 + arow) * 72 + kk + acolsel) * 2;
            ldm_x4(ah, ahi_b + aoff);
            ldm_x4(al, alo_b + aoff);
            #pragma unroll
            for (int nt = 0; nt < 4; nt++) {
                uint32_t off = ((nt * 8 + brow) * 72 + kk + bcolsel) * 2;
                ldm_x2(bh[nt], bh_b + off);
                ldm_x2(bl[nt], bl_b + off);
            }
            #pragma unroll
            for (int nt = 0; nt < 4; nt++) {
                mma_bf16(acc[nt], ah, bh[nt]);
                mma_bf16(acc[nt], al, bh[nt]);
                mma_bf16(acc[nt], ah, bl[nt]);
            }
        }
    }

    float* P = g_P[ks];
    int group = lane >> 2, tig = lane & 3;
    #pragma unroll
    for (int nt = 0; nt < 4; nt++) {
        int col = nt * 8 + tig * 2;
        int r0 = jb + wid * 16 + group;
        int r1 = r0 + 8;
        *(float2*)&P[r0 * WAY + col] = make_float2(acc[nt][0], acc[nt][1]);
        *(float2*)&P[r1 * WAY + col] = make_float2(acc[nt][2], acc[nt][3]);
    }
}

// ---------------------------------------------------------------------------
// Kernel 5: out[j,i] = -sqrt(max(A[i] + sum_ks P[ks][j,i], 0))
// ---------------------------------------------------------------------------
__global__ void finalize_kernel(float* __restrict__ out) {
    int gid = blockIdx.x * 256 + threadIdx.x;
    int base = gid * 4;
    float4 s = *(const float4*)&g_P[0][base];
    #pragma unroll
    for (int ks = 1; ks < DSPLIT; ks++) {
        float4 p = *(const float4*)&g_P[ks][base];
        s.x += p.x; s.y += p.y; s.z += p.z; s.w += p.w;
    }
    int i = base & 31;
    float4 a = *(const float4*)&g_Apart[0][i];
    #pragma unroll
    for (int c = 1; c < NCHUNK; c++) {
        float4 p = *(const float4*)&g_Apart[c][i];
        a.x += p.x; a.y += p.y; a.z += p.z; a.w += p.w;
    }
    float4 o;
    o.x = -sqrtf(fmaxf(a.x + s.x, 0.f));
    o.y = -sqrtf(fmaxf(a.y + s.y, 0.f));
    o.z = -sqrtf(fmaxf(a.z + s.z, 0.f));
    o.w = -sqrtf(fmaxf(a.w + s.w, 0.f));
    *(float4*)&out[base] = o;
}

// ---------------------------------------------------------------------------
extern "C" void kernel_launch(void* const* d_in, const int* in_sizes, int n_in,
                              void* d_out, int out_size) {
    const float* S  = (const float*)d_in[0];
    const float* Q  = (const float*)d_in[1];
    const float* W1 = (const float*)d_in[2];
    const float* b1 = (const float*)d_in[3];
    const float* W2 = (const float*)d_in[4];
    const float* b2 = (const float*)d_in[5];
    float* out = (float*)d_out;

    uv_kernel<<<160, 256>>>(S, W1, W2);
    x1split_kernel<<<MPAD * FEAT / 4 / 256, 256>>>(b1);
    gemm2_mma<<<dim3(MPAD / 64, FEAT / 64), 256>>>();
    ctx_prep_kernel<<<dim3(NCHUNK, WAY), dim3(128, 4)>>>(S, b2);
    dist_mma<<<dim3(NQ / 128, DSPLIT), 256>>>(Q);
    finalize_kernel<<<NQ * WAY / (256 * 4), 256>>>(out);
}

// round 17
// speedup vs baseline: 2.1355x; 1.0357x over previous
#include <cuda_runtime.h>
#include <cuda_bf16.h>
#include <math.h>
#include <stdint.h>

#define WAY  32
#define QRY  128
#define FEAT 640
#define NQ   (WAY*QRY)      // 4096
#define NPAIR (WAY*(WAY-1)) // 992
#define MPAD 1024

#define DSPLIT 10           // dist k-split (over K'=1280)
#define DSEG   128          // K' per split (2 chunks of 64)
#define NCHUNK 5            // ctx_prep n-chunks of 128

// Scratch (device globals; no allocation allowed)
__device__ __align__(16) float g_U[WAY*FEAT];
__device__ __align__(16) float g_V[WAY*FEAT];
__device__ __align__(16) float g_X2[MPAD*FEAT];              // gemm2 result (padded rows)
__device__ __align__(16) __nv_bfloat16 g_X1hi[MPAD*FEAT];    // X1 bf16 hi
__device__ __align__(16) __nv_bfloat16 g_X1lo[MPAD*FEAT];    // X1 bf16 lo
__device__ __align__(16) __nv_bfloat16 g_W2hi[FEAT*FEAT];    // W2 bf16 hi
__device__ __align__(16) __nv_bfloat16 g_W2lo[FEAT*FEAT];    // W2 bf16 lo
__device__ __align__(16) __nv_bfloat16 g_Bhi[WAY*2*FEAT];    // [w | -2ws] hi
__device__ __align__(16) __nv_bfloat16 g_Blo[WAY*2*FEAT];    // [w | -2ws] lo
__device__ __align__(16) float g_Apart[NCHUNK][WAY];
__device__ __align__(16) float g_P[DSPLIT][NQ*WAY];          // distance partials

__device__ __forceinline__ float leaky(float x) { return x > 0.f ? x : 0.2f * x; }

__device__ __forceinline__ uint32_t smem_u32(const void* p) {
    uint32_t a;
    asm("{ .reg .u64 t; cvta.to.shared.u64 t, %1; cvt.u32.u64 %0, t; }" : "=r"(a) : "l"(p));
    return a;
}
__device__ __forceinline__ void ldm_x4(uint32_t* r, uint32_t addr) {
    asm volatile("ldmatrix.sync.aligned.m8n8.x4.shared.b16 {%0,%1,%2,%3}, [%4];"
                 : "=r"(r[0]), "=r"(r[1]), "=r"(r[2]), "=r"(r[3]) : "r"(addr));
}
__device__ __forceinline__ void ldm_x2(uint32_t* r, uint32_t addr) {
    asm volatile("ldmatrix.sync.aligned.m8n8.x2.shared.b16 {%0,%1}, [%2];"
                 : "=r"(r[0]), "=r"(r[1]) : "r"(addr));
}
__device__ __forceinline__ void mma_bf16(float* c, const uint32_t* a, const uint32_t* b) {
    asm volatile(
        "mma.sync.aligned.m16n8k16.row.col.f32.bf16.bf16.f32 "
        "{%0,%1,%2,%3}, {%4,%5,%6,%7}, {%8,%9}, {%0,%1,%2,%3};"
        : "+f"(c[0]), "+f"(c[1]), "+f"(c[2]), "+f"(c[3])
        : "r"(a[0]), "r"(a[1]), "r"(a[2]), "r"(a[3]), "r"(b[0]), "r"(b[1]));
}
// Truncation-based hi/lo split: hi = high 16 bits, lo = trunc(v - hi). Cheap.
__device__ __forceinline__ void split4t(float4 v, uint2& hi, uint2& lo) {
    uint32_t ux = __float_as_uint(v.x), uy = __float_as_uint(v.y),
             uz = __float_as_uint(v.z), uw = __float_as_uint(v.w);
    float rx = v.x - __uint_as_float(ux & 0xFFFF0000u);
    float ry = v.y - __uint_as_float(uy & 0xFFFF0000u);
    float rz = v.z - __uint_as_float(uz & 0xFFFF0000u);
    float rw = v.w - __uint_as_float(uw & 0xFFFF0000u);
    hi.x = __byte_perm(ux, uy, 0x7632);
    hi.y = __byte_perm(uz, uw, 0x7632);
    lo.x = __byte_perm(__float_as_uint(rx), __float_as_uint(ry), 0x7632);
    lo.y = __byte_perm(__float_as_uint(rz), __float_as_uint(rw), 0x7632);
}
__device__ __forceinline__ void split1(float v, __nv_bfloat16& hi, __nv_bfloat16& lo) {
    hi = __float2bfloat16(v);
    lo = __float2bfloat16(v - __bfloat162float(hi));
}

// ---------------------------------------------------------------------------
// Kernel 1: U = S @ W1[:, :640]^T, V = S @ W1[:, 640:]^T; tail: split W2->bf16.
// ---------------------------------------------------------------------------
__global__ void uv_kernel(const float* __restrict__ S, const float* __restrict__ W1,
                          const float* __restrict__ W2) {
    __shared__ float St[320 * 33];
    int tid = threadIdx.x;
    int c = blockIdx.x * 8 + (tid >> 5);
    int i = tid & 31;
    int half = (c >= FEAT) ? 1 : 0;
    int o = c - half * FEAT;
    const float* w1row = W1 + o * (2 * FEAT) + half * FEAT;

    float a0 = 0.f, a1 = 0.f, a2 = 0.f, a3 = 0.f;
    for (int k0 = 0; k0 < FEAT; k0 += 320) {
        __syncthreads();
        #pragma unroll
        for (int r = 0; r < 10; r++) {
            int idx4 = r * 256 + tid;
            int ii = idx4 / 80;
            int kk4 = (idx4 - ii * 80) * 4;
            float4 v = *(const float4*)&S[ii * FEAT + k0 + kk4];
            St[(kk4 + 0) * 33 + ii] = v.x;
            St[(kk4 + 1) * 33 + ii] = v.y;
            St[(kk4 + 2) * 33 + ii] = v.z;
            St[(kk4 + 3) * 33 + ii] = v.w;
        }
        __syncthreads();
        #pragma unroll 4
        for (int kk = 0; kk < 320; kk += 4) {
            float4 wv = *(const float4*)&w1row[k0 + kk];
            a0 = fmaf(St[(kk + 0) * 33 + i], wv.x, a0);
            a1 = fmaf(St[(kk + 1) * 33 + i], wv.y, a1);
            a2 = fmaf(St[(kk + 2) * 33 + i], wv.z, a2);
            a3 = fmaf(St[(kk + 3) * 33 + i], wv.w, a3);
        }
    }
    float acc = (a0 + a1) + (a2 + a3);
    if (half) g_V[i * FEAT + o] = acc;
    else      g_U[i * FEAT + o] = acc;

    // Tail: W2 fp32 -> bf16 hi/lo (grid-stride).
    int nthr = gridDim.x * blockDim.x;
    for (int idx4 = blockIdx.x * blockDim.x + tid; idx4 < FEAT * FEAT / 4; idx4 += nthr) {
        float4 v = *(const float4*)&W2[idx4 * 4];
        uint2 hi, lo; split4t(v, hi, lo);
        *(uint2*)&g_W2hi[idx4 * 4] = hi;
        *(uint2*)&g_W2lo[idx4 * 4] = lo;
    }
}

// ---------------------------------------------------------------------------
// Kernel 1b: X1 = leaky(U + V + b1) -> bf16 hi/lo, once. grid 640, block 256.
// ---------------------------------------------------------------------------
__global__ void __launch_bounds__(256) x1split_kernel(const float* __restrict__ b1) {
    int idx4 = blockIdx.x * 256 + threadIdx.x;   // 0..163839 (1024 rows x 160)
    int row = idx4 / 160;
    int k4 = (idx4 - row * 160) * 4;
    float4 v;
    if (row < NPAIR) {
        int i = row / 31;
        int p = row - i * 31;
        int j = (p < i) ? p : p + 1;
        float4 u4 = *(const float4*)&g_U[i * FEAT + k4];
        float4 v4 = *(const float4*)&g_V[j * FEAT + k4];
        float4 b4 = *(const float4*)&b1[k4];
        v.x = leaky(u4.x + v4.x + b4.x);
        v.y = leaky(u4.y + v4.y + b4.y);
        v.z = leaky(u4.z + v4.z + b4.z);
        v.w = leaky(u4.w + v4.w + b4.w);
    } else v = make_float4(0.f, 0.f, 0.f, 0.f);
    uint2 hi, lo; split4t(v, hi, lo);
    *(uint2*)&g_X1hi[row * FEAT + k4] = hi;
    *(uint2*)&g_X1lo[row * FEAT + k4] = lo;
}

// ---------------------------------------------------------------------------
// Kernel 2 (mma.sync): X2 = X1 @ W2^T. Pre-split bf16 inputs, pure copies in.
// grid (16 m-tiles, 10 n-tiles), block 256 (8 warps). Block 64m x 64n,
// warp 16m x 32n. K chunks of 64. Smem row stride 72 bf16.
// Stores are unguarded: g_X2 is MPAD rows; rows >= NPAIR are exact zeros.
// ---------------------------------------------------------------------------
__global__ void __launch_bounds__(256) gemm2_mma() {
    __shared__ __align__(16) __nv_bfloat16 Xhi[64 * 72], Xlo[64 * 72];
    __shared__ __align__(16) __nv_bfloat16 Whi[64 * 72], Wlo[64 * 72];

    int tid = threadIdx.x;
    int wid = tid >> 5, lane = tid & 31;
    int m0 = blockIdx.x * 64, n0 = blockIdx.y * 64;
    int wm = wid >> 1, wn = wid & 1;      // warp: rows wm*16, cols wn*32

    uint32_t xhi_b = smem_u32(Xhi), xlo_b = smem_u32(Xlo);
    uint32_t whi_b = smem_u32(Whi), wlo_b = smem_u32(Wlo);

    float acc[4][4];
    #pragma unroll
    for (int a = 0; a < 4; a++)
        #pragma unroll
        for (int b = 0; b < 4; b++) acc[a][b] = 0.f;

    int arow = lane & 15, acolsel = (lane >> 4) * 8;
    int brow = lane & 7,  bcolsel = ((lane >> 3) & 1) * 8;

    for (int c = 0; c < 10; c++) {
        int k0 = c * 64;
        __syncthreads();
        #pragma unroll
        for (int r = 0; r < 2; r++) {
            int idx8 = r * 256 + tid;
            int rl = idx8 >> 3;
            int k8 = (idx8 & 7) * 8;
            *(uint4*)&Xhi[rl * 72 + k8] = *(const uint4*)&g_X1hi[(m0 + rl) * FEAT + k0 + k8];
            *(uint4*)&Xlo[rl * 72 + k8] = *(const uint4*)&g_X1lo[(m0 + rl) * FEAT + k0 + k8];
            *(uint4*)&Whi[rl * 72 + k8] = *(const uint4*)&g_W2hi[(n0 + rl) * FEAT + k0 + k8];
            *(uint4*)&Wlo[rl * 72 + k8] = *(const uint4*)&g_W2lo[(n0 + rl) * FEAT + k0 + k8];
        }
        __syncthreads();

        #pragma unroll
        for (int kk = 0; kk < 64; kk += 16) {
            uint32_t ah[4], al[4], bh[4][2], bl[4][2];
            uint32_t aoff = ((wm * 16 + arow) * 72 + kk + acolsel) * 2;
            ldm_x4(ah, xhi_b + aoff);
            ldm_x4(al, xlo_b + aoff);
            #pragma unroll
            for (int nt = 0; nt < 4; nt++) {
                uint32_t off = ((wn * 32 + nt * 8 + brow) * 72 + kk + bcolsel) * 2;
                ldm_x2(bh[nt], whi_b + off);
                ldm_x2(bl[nt], wlo_b + off);
            }
            #pragma unroll
            for (int nt = 0; nt < 4; nt++) {
                mma_bf16(acc[nt], ah, bh[nt]);
                mma_bf16(acc[nt], al, bh[nt]);
                mma_bf16(acc[nt], ah, bl[nt]);
            }
        }
    }

    int group = lane >> 2, tig = lane & 3;
    #pragma unroll
    for (int nt = 0; nt < 4; nt++) {
        int colb = n0 + wn * 32 + nt * 8 + tig * 2;
        int r0 = m0 + wm * 16 + group;
        int r1 = r0 + 8;
        *(float2*)&g_X2[r0 * FEAT + colb] = make_float2(acc[nt][0], acc[nt][1]);
        *(float2*)&g_X2[r1 * FEAT + colb] = make_float2(acc[nt][2], acc[nt][3]);
    }
}

// ---------------------------------------------------------------------------
// Kernel 3: ctx = (1/31) sum_p leaky(X2 + b2); w = ctx^4.
// Emits B' = [w | -2ws] bf16 hi/lo rows [32][1280], plus Apart.
// grid (5 chunks, 32 classes), block (32 n4, 8 p-groups) = 256 threads.
// Each thread: 4 UNCONDITIONAL float4 loads (64 B in flight) with a
// multiplicative mask on the p=31 slot -> real MLP, bandwidth-bound.
// ---------------------------------------------------------------------------
__global__ void __launch_bounds__(256) ctx_prep_kernel(const float* __restrict__ S,
                                                       const float* __restrict__ b2) {
    __shared__ float4 red[8][32];
    int tx = threadIdx.x;   // n4 index (0..31)
    int ty = threadIdx.y;   // p-group (0..7)
    int i = blockIdx.y;
    int n = blockIdx.x * 128 + tx * 4;

    float4 bb = *(const float4*)&b2[n];
    int rbase = i * 31;

    // 4 unconditional float4 loads (rows <= rbase+31 <= 1023, in-bounds in MPAD).
    float4 v0 = *(const float4*)&g_X2[(rbase + ty * 4 + 0) * FEAT + n];
    float4 v1 = *(const float4*)&g_X2[(rbase + ty * 4 + 1) * FEAT + n];
    float4 v2 = *(const float4*)&g_X2[(rbase + ty * 4 + 2) * FEAT + n];
    float4 v3 = *(const float4*)&g_X2[(rbase + ty * 4 + 3) * FEAT + n];
    float m3 = (ty * 4 + 3 < 31) ? 1.f : 0.f;   // only slot p=31 masked

    float4 ssum;
    ssum.x = leaky(v0.x + bb.x) + leaky(v1.x + bb.x) + leaky(v2.x + bb.x) + m3 * leaky(v3.x + bb.x);
    ssum.y = leaky(v0.y + bb.y) + leaky(v1.y + bb.y) + leaky(v2.y + bb.y) + m3 * leaky(v3.y + bb.y);
    ssum.z = leaky(v0.z + bb.z) + leaky(v1.z + bb.z) + leaky(v2.z + bb.z) + m3 * leaky(v3.z + bb.z);
    ssum.w = leaky(v0.w + bb.w) + leaky(v1.w + bb.w) + leaky(v2.w + bb.w) + m3 * leaky(v3.w + bb.w);
    red[ty][tx] = ssum;
    __syncthreads();

    if (ty == 0) {
        float4 s = red[0][tx];
        #pragma unroll
        for (int g = 1; g < 8; g++) {
            float4 p = red[g][tx];
            s.x += p.x; s.y += p.y; s.z += p.z; s.w += p.w;
        }
        float4 sv = *(const float4*)&S[i * FEAT + n];
        float asum = 0.f;
        __nv_bfloat16 wh[4], wl[4], nh[4], nl[4];
        float ss[4] = {s.x, s.y, s.z, s.w};
        float sva[4] = {sv.x, sv.y, sv.z, sv.w};
        #pragma unroll
        for (int e = 0; e < 4; e++) {
            float ctx = ss[e] * (1.0f / 31.0f);
            float c2 = ctx * ctx;
            float w = c2 * c2;
            float sval = sva[e];
            split1(w, wh[e], wl[e]);
            split1(-2.0f * w * sval, nh[e], nl[e]);
            asum = fmaf(w, sval * sval, asum);
        }
        // Pack 4 bf16 -> uint2 stores.
        uint2 u;
        u.x = (uint32_t)__bfloat16_as_ushort(wh[0]) | ((uint32_t)__bfloat16_as_ushort(wh[1]) << 16);
        u.y = (uint32_t)__bfloat16_as_ushort(wh[2]) | ((uint32_t)__bfloat16_as_ushort(wh[3]) << 16);
        *(uint2*)&g_Bhi[i * 2 * FEAT + n] = u;
        u.x = (uint32_t)__bfloat16_as_ushort(wl[0]) | ((uint32_t)__bfloat16_as_ushort(wl[1]) << 16);
        u.y = (uint32_t)__bfloat16_as_ushort(wl[2]) | ((uint32_t)__bfloat16_as_ushort(wl[3]) << 16);
        *(uint2*)&g_Blo[i * 2 * FEAT + n] = u;
        u.x = (uint32_t)__bfloat16_as_ushort(nh[0]) | ((uint32_t)__bfloat16_as_ushort(nh[1]) << 16);
        u.y = (uint32_t)__bfloat16_as_ushort(nh[2]) | ((uint32_t)__bfloat16_as_ushort(nh[3]) << 16);
        *(uint2*)&g_Bhi[i * 2 * FEAT + FEAT + n] = u;
        u.x = (uint32_t)__bfloat16_as_ushort(nl[0]) | ((uint32_t)__bfloat16_as_ushort(nl[1]) << 16);
        u.y = (uint32_t)__bfloat16_as_ushort(nl[2]) | ((uint32_t)__bfloat16_as_ushort(nl[3]) << 16);
        *(uint2*)&g_Blo[i * 2 * FEAT + FEAT + n] = u;

        // Warp reduction of asum over the 32 lanes of ty==0.
        #pragma unroll
        for (int off = 16; off > 0; off >>= 1)
            asum += __shfl_down_sync(0xFFFFFFFF, asum, off);
        if (tx == 0) g_Apart[blockIdx.x][i] = asum;
    }
}

// ---------------------------------------------------------------------------
// Kernel 4 (mma.sync): dist partials. D = [Q^2 | Q] @ B'^T over K'=1280.
// grid (32 m-tiles of 128, DSPLIT=10), block 256 (8 warps).
// Warp tile 16m x 32n. Segment is purely Q^2 (ks<5) or Q (ks>=5).
// ---------------------------------------------------------------------------
__global__ void __launch_bounds__(256) dist_mma(const float* __restrict__ Q) {
    __shared__ __align__(16) __nv_bfloat16 Ahi[128 * 72], Alo[128 * 72];
    __shared__ __align__(16) __nv_bfloat16 Bh[32 * 72], Bl[32 * 72];

    int tid = threadIdx.x;
    int wid = tid >> 5, lane = tid & 31;
    int jb = blockIdx.x * 128;
    int ks = blockIdx.y;
    bool useq = (ks >= 5);
    int kbase = ks * DSEG;

    uint32_t ahi_b = smem_u32(Ahi), alo_b = smem_u32(Alo);
    uint32_t bh_b = smem_u32(Bh), bl_b = smem_u32(Bl);

    float acc[4][4];
    #pragma unroll
    for (int a = 0; a < 4; a++)
        #pragma unroll
        for (int b = 0; b < 4; b++) acc[a][b] = 0.f;

    int arow = lane & 15, acolsel = (lane >> 4) * 8;
    int brow = lane & 7,  bcolsel = ((lane >> 3) & 1) * 8;

    #pragma unroll
    for (int c = 0; c < 2; c++) {
        int kg = kbase + c * 64;
        int f0 = useq ? (kg - FEAT) : kg;
        __syncthreads();
        #pragma unroll
        for (int r = 0; r < 8; r++) {
            int idx4 = r * 256 + tid;
            int m  = idx4 >> 4;
            int k4 = (idx4 & 15) * 4;
            float4 v = *(const float4*)&Q[(jb + m) * FEAT + f0 + k4];
            if (!useq) { v.x *= v.x; v.y *= v.y; v.z *= v.z; v.w *= v.w; }
            uint2 hi, lo; split4t(v, hi, lo);
            *(uint2*)&Ahi[m * 72 + k4] = hi;
            *(uint2*)&Alo[m * 72 + k4] = lo;
        }
        {
            int nl = tid >> 3;
            int k8 = (tid & 7) * 8;
            *(uint4*)&Bh[nl * 72 + k8] = *(const uint4*)&g_Bhi[nl * 2 * FEAT + kg + k8];
            *(uint4*)&Bl[nl * 72 + k8] = *(const uint4*)&g_Blo[nl * 2 * FEAT + kg + k8];
        }
        __syncthreads();

        #pragma unroll
        for (int kk = 0; kk < 64; kk += 16) {
            uint32_t ah[4], al[4], bh[4][2], bl[4][2];
            uint32_t aoff = ((wid * 16 + arow) * 72 + kk + acolsel) * 2;
            ldm_x4(ah, ahi_b + aoff);
            ldm_x4(al, alo_b + aoff);
            #pragma unroll
            for (int nt = 0; nt < 4; nt++) {
                uint32_t off = ((nt * 8 + brow) * 72 + kk + bcolsel) * 2;
                ldm_x2(bh[nt], bh_b + off);
                ldm_x2(bl[nt], bl_b + off);
            }
            #pragma unroll
            for (int nt = 0; nt < 4; nt++) {
                mma_bf16(acc[nt], ah, bh[nt]);
                mma_bf16(acc[nt], al, bh[nt]);
                mma_bf16(acc[nt], ah, bl[nt]);
            }
        }
    }

    float* P = g_P[ks];
    int group = lane >> 2, tig = lane & 3;
    #pragma unroll
    for (int nt = 0; nt < 4; nt++) {
        int col = nt * 8 + tig * 2;
        int r0 = jb + wid * 16 + group;
        int r1 = r0 + 8;
        *(float2*)&P[r0 * WAY + col] = make_float2(acc[nt][0], acc[nt][1]);
        *(float2*)&P[r1 * WAY + col] = make_float2(acc[nt][2], acc[nt][3]);
    }
}

// ---------------------------------------------------------------------------
// Kernel 5: out[j,i] = -sqrt(max(A[i] + sum_ks P[ks][j,i], 0))
// ---------------------------------------------------------------------------
__global__ void finalize_kernel(float* __restrict__ out) {
    int gid = blockIdx.x * 256 + threadIdx.x;
    int base = gid * 4;
    float4 s = *(const float4*)&g_P[0][base];
    #pragma unroll
    for (int ks = 1; ks < DSPLIT; ks++) {
        float4 p = *(const float4*)&g_P[ks][base];
        s.x += p.x; s.y += p.y; s.z += p.z; s.w += p.w;
    }
    int i = base & 31;
    float4 a = *(const float4*)&g_Apart[0][i];
    #pragma unroll
    for (int c = 1; c < NCHUNK; c++) {
        float4 p = *(const float4*)&g_Apart[c][i];
        a.x += p.x; a.y += p.y; a.z += p.z; a.w += p.w;
    }
    float4 o;
    o.x = -sqrtf(fmaxf(a.x + s.x, 0.f));
    o.y = -sqrtf(fmaxf(a.y + s.y, 0.f));
    o.z = -sqrtf(fmaxf(a.z + s.z, 0.f));
    o.w = -sqrtf(fmaxf(a.w + s.w, 0.f));
    *(float4*)&out[base] = o;
}

// ---------------------------------------------------------------------------
extern "C" void kernel_launch(void* const* d_in, const int* in_sizes, int n_in,
                              void* d_out, int out_size) {
    const float* S  = (const float*)d_in[0];
    const float* Q  = (const float*)d_in[1];
    const float* W1 = (const float*)d_in[2];
    const float* b1 = (const float*)d_in[3];
    const float* W2 = (const float*)d_in[4];
    const float* b2 = (const float*)d_in[5];
    float* out = (float*)d_out;

    uv_kernel<<<160, 256>>>(S, W1, W2);
    x1split_kernel<<<MPAD * FEAT / 4 / 256, 256>>>(b1);
    gemm2_mma<<<dim3(MPAD / 64, FEAT / 64), 256>>>();
    ctx_prep_kernel<<<dim3(NCHUNK, WAY), dim3(32, 8)>>>(S, b2);
    dist_mma<<<dim3(NQ / 128, DSPLIT), 256>>>(Q);
    finalize_kernel<<<NQ * WAY / (256 * 4), 256>>>(out);
}